// round 10
// baseline (speedup 1.0000x reference)
#include <cuda_runtime.h>
#include <math.h>
#include <stdint.h>

#define L_SEQ  2048
#define NB     4
#define EMB    768
#define NHEAD  12
#define DH     64
#define ROWS   (L_SEQ * NB)      // 8192
#define E3     (3 * EMB)         // 2304
#define E4     (4 * EMB)         // 3072

// ---------------- scratch ----------------
__device__ float g_h   [ (size_t)ROWS * EMB ];   // LN out, tf32+permuted
__device__ float g_qkv [ (size_t)ROWS * E3  ];   // normal layout
__device__ float g_attn[ (size_t)ROWS * EMB ];   // tf32+permuted
__device__ float g_x1  [ (size_t)ROWS * EMB ];   // normal
__device__ float g_f   [ (size_t)ROWS * E4  ];   // tf32+permuted
__device__ float g_wqkv [ (size_t)E3  * EMB ];   // permuted weights
__device__ float g_wout [ (size_t)EMB * EMB ];
__device__ float g_wfc  [ (size_t)E4  * EMB ];
__device__ float g_wproj[ (size_t)EMB * E4  ];

#define CVT_TF32(d, s) asm volatile("cvt.rna.tf32.f32 %0, %1;" : "=r"(d) : "f"(s))

__device__ __forceinline__ uint32_t smem_u32(const void* p) {
    uint32_t a;
    asm("{ .reg .u64 t; cvta.to.shared.u64 t, %1; cvt.u32.u64 %0, t; }" : "=r"(a) : "l"(p));
    return a;
}
__device__ __forceinline__ void cp16(uint32_t dst, const void* src) {
    asm volatile("cp.async.cg.shared.global [%0], [%1], 16;" :: "r"(dst), "l"(src));
}
#define CP_COMMIT() asm volatile("cp.async.commit_group;" ::: "memory")
#define CP_WAIT(n)  asm volatile("cp.async.wait_group %0;" :: "n"(n) : "memory")

__device__ __forceinline__ float ex2f(float x) {
    float y; asm("ex2.approx.f32 %0, %1;" : "=f"(y) : "f"(x)); return y;
}
__device__ __forceinline__ void mma8v(float* c,
                                      uint32_t a0, uint32_t a1, uint32_t a2, uint32_t a3,
                                      uint32_t b0, uint32_t b1) {
    asm volatile(
        "mma.sync.aligned.m16n8k8.row.col.f32.tf32.tf32.f32 "
        "{%0,%1,%2,%3}, {%4,%5,%6,%7}, {%8,%9}, {%0,%1,%2,%3};"
        : "+f"(c[0]), "+f"(c[1]), "+f"(c[2]), "+f"(c[3])
        : "r"(a0), "r"(a1), "r"(a2), "r"(a3), "r"(b0), "r"(b1));
}

// ---------------- merged weight permute + tf32 round (single launch) ----------------
#define S0 (E3 * EMB)
#define S1 (EMB * EMB)
#define S2 (E4 * EMB)
#define S3 (EMB * E4)
__global__ __launch_bounds__(256) void permute_all(
    const float* __restrict__ w0, float* __restrict__ o0,
    const float* __restrict__ w1, float* __restrict__ o1,
    const float* __restrict__ w2, float* __restrict__ o2,
    const float* __restrict__ w3, float* __restrict__ o3)
{
    int i = blockIdx.x * 256 + threadIdx.x;
    const float* in; float* out; int idx = i;
    if (idx < S0)              { in = w0; out = o0; }
    else if ((idx -= S0) < S1) { in = w1; out = o1; }
    else if ((idx -= S1) < S2) { in = w2; out = o2; }
    else {
        idx -= S2;
        if (idx >= S3) return;
        in = w3; out = o3;
    }
    int j  = idx & 15;
    int pj = ((j & 3) << 2) | (j >> 2);
    uint32_t v; CVT_TF32(v, in[idx]);
    ((uint32_t*)out)[(idx & ~15) | pj] = v;
}

// ---------------- LayerNorm -> tf32 + permuted output ----------------
__global__ __launch_bounds__(256) void ln_kernel(const float* __restrict__ x,
                                                 const float* __restrict__ w,
                                                 const float* __restrict__ b,
                                                 float* __restrict__ out)
{
    int row = blockIdx.x;
    const float* xr = x + (size_t)row * EMB;
    uint32_t* orow = (uint32_t*)(out + (size_t)row * EMB);
    int t = threadIdx.x;

    float v[3];
    float sum = 0.f, sq = 0.f;
#pragma unroll
    for (int i = 0; i < 3; i++) {
        v[i] = xr[t + 256 * i];
        sum += v[i];
        sq  += v[i] * v[i];
    }
    __shared__ float s1[8], s2[8], bc[2];
    for (int o = 16; o > 0; o >>= 1) {
        sum += __shfl_xor_sync(0xffffffffu, sum, o);
        sq  += __shfl_xor_sync(0xffffffffu, sq,  o);
    }
    int wid = t >> 5, lid = t & 31;
    if (lid == 0) { s1[wid] = sum; s2[wid] = sq; }
    __syncthreads();
    if (t == 0) {
        float ts = 0.f, tq = 0.f;
#pragma unroll
        for (int i = 0; i < 8; i++) { ts += s1[i]; tq += s2[i]; }
        float mu  = ts * (1.0f / EMB);
        float var = tq * (1.0f / EMB) - mu * mu;
        bc[0] = mu;
        bc[1] = rsqrtf(var + 1e-5f);
    }
    __syncthreads();
    float mu = bc[0], rstd = bc[1];
    int j  = t & 15;
    int pj = ((j & 3) << 2) | (j >> 2);
#pragma unroll
    for (int i = 0; i < 3; i++) {
        int c = t + 256 * i;
        float y = (v[i] - mu) * rstd * w[c] + b[c];
        uint32_t u; CVT_TF32(u, y);
        orow[(c & ~15) | pj] = u;
    }
}

// ---------------- cp.async tf32 GEMM, k32 stages, GS=3 ----------------
// C = A[M,K] @ B[N,K]^T + bias (+EPI). A,B tf32+k-permuted in gmem.
// 128x128 tile, 256 thr, 8 warps 2x4, stage = 128x32 per operand (16KB).
#define GS 3
#define GBUF (128 * 32)                     // floats per operand stage (16KB)
#define GT_SMEM (GS * 2 * GBUF * 4)         // 98304 bytes

template <int EPI>
__global__ __launch_bounds__(256, 2) void gemm_cp(
    const float* __restrict__ A, const float* __restrict__ B,
    const float* __restrict__ bias, const float* __restrict__ res,
    float* __restrict__ C, int M, int N, int K)
{
    extern __shared__ float smem[];
    const uint32_t sb = smem_u32(smem);

    const int tid  = threadIdx.x;
    const int wid  = tid >> 5;
    const int lane = tid & 31;
    const int g = lane >> 2, t = lane & 3;

    const int bm = blockIdx.y * 128;
    const int bn = blockIdx.x * 128;
    const int wm = (wid >> 2) * 64;
    const int wn = (wid & 3) * 32;

    // ---- staging: 4 x 16B of A + 4 x 16B of B per thread per k32 chunk ----
    const int lr = tid >> 1;                 // row 0..127
    const int hc = (tid & 1) * 2;            // 16B-unit pair within a 16-float block
    const int sw = ((lr & 3) ^ ((lr >> 2) & 3)) << 2;
    const float* Ap = A + (size_t)(bm + lr) * K + hc * 4;
    const float* Bp = B + (size_t)(bn + lr) * K + hc * 4;
    // dst offsets for (block b in {0,1}) x (unit u in {hc, hc+1})
    uint32_t dA[4], dB[4];
#pragma unroll
    for (int b = 0; b < 2; b++)
#pragma unroll
        for (int u = 0; u < 2; u++) {
            uint32_t off = (uint32_t)(lr * 32 + b * 16 + ((4 * (hc + u)) ^ sw)) * 4;
            dA[b * 2 + u] = sb + off;
            dB[b * 2 + u] = sb + off + GS * GBUF * 4;
        }

    // ---- fragment read columns ----
    const int cA0 = (4 * t) ^ (((g & 3) ^ ((g >> 2) & 3)) << 2);
    const int cA8 = (4 * t) ^ (((g & 3) ^ (((g >> 2) + 2) & 3)) << 2);
    int cB[4];
#pragma unroll
    for (int nt = 0; nt < 4; nt++)
        cB[nt] = (4 * t) ^ (((g & 3) ^ (((g >> 2) + 2 * nt) & 3)) << 2);

    float acc[4][4][4];
#pragma unroll
    for (int i = 0; i < 4; i++)
#pragma unroll
        for (int j = 0; j < 4; j++)
#pragma unroll
            for (int q = 0; q < 4; q++) acc[i][j][q] = 0.f;

    const int NC = K / 32;

    // preload chunks 0..GS-2
#pragma unroll
    for (int c = 0; c < GS - 1; c++) {
        uint32_t so = (uint32_t)(c * GBUF * 4);
        const float* a = Ap + (size_t)c * 32;
        const float* b = Bp + (size_t)c * 32;
#pragma unroll
        for (int i = 0; i < 4; i++) {
            int goff = (i >> 1) * 16 + (i & 1) * 4;   // b*16 + u*4
            cp16(dA[i] + so, a + goff);
            cp16(dB[i] + so, b + goff);
        }
        CP_COMMIT();
    }

    for (int c = 0; c < NC; c++) {
        CP_WAIT(GS - 2);
        __syncthreads();

        int nc = c + GS - 1;
        if (nc < NC) {
            uint32_t so = (uint32_t)((nc % GS) * GBUF * 4);
            const float* a = Ap + (size_t)nc * 32;
            const float* b = Bp + (size_t)nc * 32;
#pragma unroll
            for (int i = 0; i < 4; i++) {
                int goff = (i >> 1) * 16 + (i & 1) * 4;
                cp16(dA[i] + so, a + goff);
                cp16(dB[i] + so, b + goff);
            }
        }
        CP_COMMIT();

        const int s = c % GS;
        const uint32_t* Ab = (const uint32_t*)(smem + s * GBUF);
        const uint32_t* Bb = (const uint32_t*)(smem + (GS + s) * GBUF);

#pragma unroll
        for (int kb2 = 0; kb2 < 2; kb2++) {
            const int ko = kb2 * 16;
            uint4 br[4];
#pragma unroll
            for (int nt = 0; nt < 4; nt++)
                br[nt] = *(const uint4*)&Bb[(wn + nt * 8 + g) * 32 + ko + cB[nt]];

#pragma unroll
            for (int mt = 0; mt < 4; mt++) {
                const int r0 = wm + mt * 16 + g;
                uint4 ar0 = *(const uint4*)&Ab[r0 * 32 + ko + cA0];
                uint4 ar1 = *(const uint4*)&Ab[(r0 + 8) * 32 + ko + cA8];
#pragma unroll
                for (int nt = 0; nt < 4; nt++) {
                    mma8v(acc[mt][nt], ar0.x, ar1.x, ar0.y, ar1.y, br[nt].x, br[nt].y);
                    mma8v(acc[mt][nt], ar0.z, ar1.z, ar0.w, ar1.w, br[nt].z, br[nt].w);
                }
            }
        }
    }

    // ---- epilogue ----
#pragma unroll
    for (int mt = 0; mt < 4; mt++) {
#pragma unroll
        for (int nt = 0; nt < 4; nt++) {
            int gcol = bn + wn + nt * 8 + 2 * t;
            float2 bv = *(const float2*)&bias[gcol];
            int r0 = bm + wm + mt * 16 + g;
#pragma unroll
            for (int hrow = 0; hrow < 2; hrow++) {
                int grow = r0 + hrow * 8;
                float c0 = acc[mt][nt][2 * hrow]     + bv.x;
                float c1 = acc[mt][nt][2 * hrow + 1] + bv.y;
                if (EPI == 1) {
                    size_t gidx = (size_t)grow * N + gcol;
                    float2 rv = *(const float2*)&res[gidx];
                    c0 += rv.x; c1 += rv.y;
                    *(float2*)&C[gidx] = make_float2(c0, c1);
                } else if (EPI == 0) {
                    size_t gidx = (size_t)grow * N + gcol;
                    *(float2*)&C[gidx] = make_float2(c0, c1);
                } else {             // QuickGELU -> tf32 + permuted
                    c0 = c0 / (1.f + __expf(-1.702f * c0));
                    c1 = c1 / (1.f + __expf(-1.702f * c1));
                    int p  = gcol & 15;
                    int pp = ((p & 3) << 2) | (p >> 2);
                    size_t b16 = (size_t)grow * N + (gcol & ~15);
                    uint32_t u0, u1;
                    CVT_TF32(u0, c0); CVT_TF32(u1, c1);
                    ((uint32_t*)C)[b16 + pp]     = u0;
                    ((uint32_t*)C)[b16 + pp + 4] = u1;
                }
            }
        }
    }
}

// ---------------- Flash attention via mma.sync tf32; permuted tf32 output ----------------
#define KS_STR 68
#define VS_STR 72
#define PS_STR 68
#define ATT_SMEM ((64 * KS_STR + 64 * VS_STR + 4 * 16 * PS_STR) * 4)

__global__ __launch_bounds__(128) void attn_mma(const float* __restrict__ qkv,
                                                float* __restrict__ o)
{
    extern __shared__ float asmem[];
    float* Ks = asmem;
    float* Vs = asmem + 64 * KS_STR;
    float* Ps = asmem + 64 * KS_STR + 64 * VS_STR;

    const int tid  = threadIdx.x;
    const int w    = tid >> 5;
    const int lane = tid & 31;
    const int g = lane >> 2, t = lane & 3;
    const int qb = blockIdx.x * 64 + w * 16;
    const int h = blockIdx.y, n = blockIdx.z;

    const float qscale = 0.125f * 1.44269504088896f;

    uint32_t aq[8][4];
    {
        size_t r0 = ((size_t)(qb + g) * NB + n) * E3 + h * DH;
        size_t r1 = ((size_t)(qb + g + 8) * NB + n) * E3 + h * DH;
#pragma unroll
        for (int ch = 0; ch < 8; ch++) {
            float v0 = qkv[r0 + ch * 8 + t]     * qscale;
            float v1 = qkv[r1 + ch * 8 + t]     * qscale;
            float v2 = qkv[r0 + ch * 8 + t + 4] * qscale;
            float v3 = qkv[r1 + ch * 8 + t + 4] * qscale;
            CVT_TF32(aq[ch][0], v0); CVT_TF32(aq[ch][1], v1);
            CVT_TF32(aq[ch][2], v2); CVT_TF32(aq[ch][3], v3);
        }
    }

    float oc[8][4];
#pragma unroll
    for (int i = 0; i < 8; i++)
#pragma unroll
        for (int j = 0; j < 4; j++) oc[i][j] = 0.f;
    float m0 = -1e30f, m1 = -1e30f, l0 = 0.f, l1 = 0.f;

    const int srow  = tid >> 1;
    const int shalf = (tid & 1) * 32;

    for (int kb = 0; kb < L_SEQ / 64; kb++) {
        size_t kbase = ((size_t)(kb * 64 + srow) * NB + n) * E3 + EMB + h * DH + shalf;
        float4 kr[8];
#pragma unroll
        for (int i = 0; i < 8; i++) kr[i] = *(const float4*)&qkv[kbase + 4 * i];
        __syncthreads();
        {
            uint32_t* ks = (uint32_t*)&Ks[srow * KS_STR + shalf];
#pragma unroll
            for (int i = 0; i < 8; i++) {
                uint4 cv;
                CVT_TF32(cv.x, kr[i].x); CVT_TF32(cv.y, kr[i].y);
                CVT_TF32(cv.z, kr[i].z); CVT_TF32(cv.w, kr[i].w);
                *(uint4*)&ks[4 * i] = cv;
            }
        }
        size_t vbase = kbase + EMB;
#pragma unroll
        for (int i = 0; i < 8; i++) kr[i] = *(const float4*)&qkv[vbase + 4 * i];
        {
            uint32_t* vs = (uint32_t*)&Vs[srow * VS_STR + shalf];
#pragma unroll
            for (int i = 0; i < 8; i++) {
                uint4 cv;
                CVT_TF32(cv.x, kr[i].x); CVT_TF32(cv.y, kr[i].y);
                CVT_TF32(cv.z, kr[i].z); CVT_TF32(cv.w, kr[i].w);
                *(uint4*)&vs[4 * i] = cv;
            }
        }
        __syncthreads();

        float sc[8][4];
#pragma unroll
        for (int i = 0; i < 8; i++)
#pragma unroll
            for (int j = 0; j < 4; j++) sc[i][j] = 0.f;

        const uint32_t* ksb = (const uint32_t*)Ks;
#pragma unroll
        for (int nt = 0; nt < 8; nt++) {
#pragma unroll
            for (int ch = 0; ch < 8; ch++) {
                uint32_t b0 = ksb[(nt * 8 + g) * KS_STR + ch * 8 + t];
                uint32_t b1 = ksb[(nt * 8 + g) * KS_STR + ch * 8 + t + 4];
                mma8v(sc[nt], aq[ch][0], aq[ch][1], aq[ch][2], aq[ch][3], b0, b1);
            }
        }

        float tm0 = -1e30f, tm1 = -1e30f;
#pragma unroll
        for (int nt = 0; nt < 8; nt++) {
            tm0 = fmaxf(tm0, fmaxf(sc[nt][0], sc[nt][1]));
            tm1 = fmaxf(tm1, fmaxf(sc[nt][2], sc[nt][3]));
        }
        tm0 = fmaxf(tm0, __shfl_xor_sync(0xffffffffu, tm0, 1));
        tm0 = fmaxf(tm0, __shfl_xor_sync(0xffffffffu, tm0, 2));
        tm1 = fmaxf(tm1, __shfl_xor_sync(0xffffffffu, tm1, 1));
        tm1 = fmaxf(tm1, __shfl_xor_sync(0xffffffffu, tm1, 2));

        float nm0 = fmaxf(m0, tm0), nm1 = fmaxf(m1, tm1);
        float al0 = ex2f(m0 - nm0), al1 = ex2f(m1 - nm1);
        m0 = nm0; m1 = nm1;

        float s0 = 0.f, s1 = 0.f;
#pragma unroll
        for (int nt = 0; nt < 8; nt++) {
            sc[nt][0] = ex2f(sc[nt][0] - m0);
            sc[nt][1] = ex2f(sc[nt][1] - m0);
            sc[nt][2] = ex2f(sc[nt][2] - m1);
            sc[nt][3] = ex2f(sc[nt][3] - m1);
            s0 += sc[nt][0] + sc[nt][1];
            s1 += sc[nt][2] + sc[nt][3];
        }
        s0 += __shfl_xor_sync(0xffffffffu, s0, 1);
        s0 += __shfl_xor_sync(0xffffffffu, s0, 2);
        s1 += __shfl_xor_sync(0xffffffffu, s1, 1);
        s1 += __shfl_xor_sync(0xffffffffu, s1, 2);
        l0 = l0 * al0 + s0;
        l1 = l1 * al1 + s1;
#pragma unroll
        for (int nt = 0; nt < 8; nt++) {
            oc[nt][0] *= al0; oc[nt][1] *= al0;
            oc[nt][2] *= al1; oc[nt][3] *= al1;
        }

        uint32_t* pw = (uint32_t*)(Ps + w * 16 * PS_STR);
        __syncwarp();
#pragma unroll
        for (int nt = 0; nt < 8; nt++) {
            uint2 p0, p1;
            CVT_TF32(p0.x, sc[nt][0]); CVT_TF32(p0.y, sc[nt][1]);
            CVT_TF32(p1.x, sc[nt][2]); CVT_TF32(p1.y, sc[nt][3]);
            *(uint2*)&pw[g * PS_STR + nt * 8 + 2 * t]       = p0;
            *(uint2*)&pw[(g + 8) * PS_STR + nt * 8 + 2 * t] = p1;
        }
        __syncwarp();

        const uint32_t* vsb = (const uint32_t*)Vs;
#pragma unroll
        for (int ch = 0; ch < 8; ch++) {
            uint32_t ap0 = pw[g * PS_STR + ch * 8 + t];
            uint32_t ap1 = pw[(g + 8) * PS_STR + ch * 8 + t];
            uint32_t ap2 = pw[g * PS_STR + ch * 8 + t + 4];
            uint32_t ap3 = pw[(g + 8) * PS_STR + ch * 8 + t + 4];
#pragma unroll
            for (int nt = 0; nt < 8; nt++) {
                uint32_t b0 = vsb[(ch * 8 + t) * VS_STR + nt * 8 + g];
                uint32_t b1 = vsb[(ch * 8 + t + 4) * VS_STR + nt * 8 + g];
                mma8v(oc[nt], ap0, ap1, ap2, ap3, b0, b1);
            }
        }
    }

    float i0 = 1.f / l0, i1 = 1.f / l1;
    size_t o0 = ((size_t)(qb + g) * NB + n) * EMB + h * DH;
    size_t o1 = ((size_t)(qb + g + 8) * NB + n) * EMB + h * DH;
#pragma unroll
    for (int nt = 0; nt < 8; nt++) {
        int d  = nt * 8 + 2 * t;
        int p  = d & 15;
        int pp = ((p & 3) << 2) | (p >> 2);
        int b16 = d & ~15;
        uint32_t u0, u1, u2, u3;
        CVT_TF32(u0, oc[nt][0] * i0); CVT_TF32(u1, oc[nt][1] * i0);
        CVT_TF32(u2, oc[nt][2] * i1); CVT_TF32(u3, oc[nt][3] * i1);
        ((uint32_t*)o)[o0 + b16 + pp]     = u0;
        ((uint32_t*)o)[o0 + b16 + pp + 4] = u1;
        ((uint32_t*)o)[o1 + b16 + pp]     = u2;
        ((uint32_t*)o)[o1 + b16 + pp + 4] = u3;
    }
}

// ---------------- launch ----------------
extern "C" void kernel_launch(void* const* d_in, const int* in_sizes, int n_in,
                              void* d_out, int out_size)
{
    const float* x      = (const float*)d_in[0];
    const float* ln1_w  = (const float*)d_in[1];
    const float* ln1_b  = (const float*)d_in[2];
    const float* w_qkv  = (const float*)d_in[3];
    const float* b_qkv  = (const float*)d_in[4];
    const float* w_out  = (const float*)d_in[5];
    const float* b_out  = (const float*)d_in[6];
    const float* ln2_w  = (const float*)d_in[7];
    const float* ln2_b  = (const float*)d_in[8];
    const float* w_fc   = (const float*)d_in[9];
    const float* b_fc   = (const float*)d_in[10];
    const float* w_proj = (const float*)d_in[11];
    const float* b_proj = (const float*)d_in[12];
    float* out = (float*)d_out;

    float *h, *qkv, *attn, *x1, *f, *wqkv, *wout, *wfc, *wproj;
    cudaGetSymbolAddress((void**)&h,     g_h);
    cudaGetSymbolAddress((void**)&qkv,   g_qkv);
    cudaGetSymbolAddress((void**)&attn,  g_attn);
    cudaGetSymbolAddress((void**)&x1,    g_x1);
    cudaGetSymbolAddress((void**)&f,     g_f);
    cudaGetSymbolAddress((void**)&wqkv,  g_wqkv);
    cudaGetSymbolAddress((void**)&wout,  g_wout);
    cudaGetSymbolAddress((void**)&wfc,   g_wfc);
    cudaGetSymbolAddress((void**)&wproj, g_wproj);

    cudaFuncSetAttribute(gemm_cp<0>, cudaFuncAttributeMaxDynamicSharedMemorySize, GT_SMEM);
    cudaFuncSetAttribute(gemm_cp<1>, cudaFuncAttributeMaxDynamicSharedMemorySize, GT_SMEM);
    cudaFuncSetAttribute(gemm_cp<2>, cudaFuncAttributeMaxDynamicSharedMemorySize, GT_SMEM);
    cudaFuncSetAttribute(attn_mma,   cudaFuncAttributeMaxDynamicSharedMemorySize, ATT_SMEM);

    // merged weight pre-pass
    int ptotal = S0 + S1 + S2 + S3;
    permute_all<<<(ptotal + 255) / 256, 256>>>(w_qkv, wqkv, w_out, wout,
                                               w_fc, wfc, w_proj, wproj);

    ln_kernel<<<ROWS, 256>>>(x, ln1_w, ln1_b, h);
    gemm_cp<0><<<dim3(E3 / 128, ROWS / 128), 256, GT_SMEM>>>(h, wqkv, b_qkv, nullptr, qkv,
                                                             ROWS, E3, EMB);
    attn_mma<<<dim3(L_SEQ / 64, NHEAD, NB), 128, ATT_SMEM>>>(qkv, attn);
    gemm_cp<1><<<dim3(EMB / 128, ROWS / 128), 256, GT_SMEM>>>(attn, wout, b_out, x, x1,
                                                              ROWS, EMB, EMB);
    ln_kernel<<<ROWS, 256>>>(x1, ln2_w, ln2_b, h);
    gemm_cp<2><<<dim3(E4 / 128, ROWS / 128), 256, GT_SMEM>>>(h, wfc, b_fc, nullptr, f,
                                                             ROWS, E4, EMB);
    gemm_cp<1><<<dim3(EMB / 128, ROWS / 128), 256, GT_SMEM>>>(f, wproj, b_proj, x1, out,
                                                              ROWS, EMB, E4);
}

// round 11
// speedup vs baseline: 1.0716x; 1.0716x over previous
#include <cuda_runtime.h>
#include <math.h>
#include <stdint.h>

#define L_SEQ  2048
#define NB     4
#define EMB    768
#define NHEAD  12
#define DH     64
#define ROWS   (L_SEQ * NB)      // 8192
#define E3     (3 * EMB)         // 2304
#define E4     (4 * EMB)         // 3072

// ---------------- scratch ----------------
__device__ float g_h   [ (size_t)ROWS * EMB ];
__device__ float g_qkv [ (size_t)ROWS * E3  ];
__device__ float g_attn[ (size_t)ROWS * EMB ];
__device__ float g_x1  [ (size_t)ROWS * EMB ];
__device__ float g_f   [ (size_t)ROWS * E4  ];
__device__ float g_wqkv [ (size_t)E3  * EMB ];
__device__ float g_wout [ (size_t)EMB * EMB ];
__device__ float g_wfc  [ (size_t)E4  * EMB ];
__device__ float g_wproj[ (size_t)EMB * E4  ];

#define CVT_TF32(d, s) asm volatile("cvt.rna.tf32.f32 %0, %1;" : "=r"(d) : "f"(s))

__device__ __forceinline__ uint32_t smem_u32(const void* p) {
    uint32_t a;
    asm("{ .reg .u64 t; cvta.to.shared.u64 t, %1; cvt.u32.u64 %0, t; }" : "=r"(a) : "l"(p));
    return a;
}
__device__ __forceinline__ void cp16(uint32_t dst, const void* src) {
    asm volatile("cp.async.cg.shared.global [%0], [%1], 16;" :: "r"(dst), "l"(src));
}
#define CP_COMMIT() asm volatile("cp.async.commit_group;" ::: "memory")
#define CP_WAIT(n)  asm volatile("cp.async.wait_group %0;" :: "n"(n) : "memory")

__device__ __forceinline__ float ex2f(float x) {
    float y; asm("ex2.approx.f32 %0, %1;" : "=f"(y) : "f"(x)); return y;
}
__device__ __forceinline__ void mma8v(float* c,
                                      uint32_t a0, uint32_t a1, uint32_t a2, uint32_t a3,
                                      uint32_t b0, uint32_t b1) {
    asm volatile(
        "mma.sync.aligned.m16n8k8.row.col.f32.tf32.tf32.f32 "
        "{%0,%1,%2,%3}, {%4,%5,%6,%7}, {%8,%9}, {%0,%1,%2,%3};"
        : "+f"(c[0]), "+f"(c[1]), "+f"(c[2]), "+f"(c[3])
        : "r"(a0), "r"(a1), "r"(a2), "r"(a3), "r"(b0), "r"(b1));
}
__device__ __forceinline__ int swr(int r) { return (((r & 3) ^ ((r >> 2) & 3)) << 2); }

// ---------------- merged weight permute + tf32 round ----------------
#define S0 (E3 * EMB)
#define S1 (EMB * EMB)
#define S2 (E4 * EMB)
#define S3 (EMB * E4)
__global__ __launch_bounds__(256) void permute_all(
    const float* __restrict__ w0, float* __restrict__ o0,
    const float* __restrict__ w1, float* __restrict__ o1,
    const float* __restrict__ w2, float* __restrict__ o2,
    const float* __restrict__ w3, float* __restrict__ o3)
{
    int i = blockIdx.x * 256 + threadIdx.x;
    const float* in; float* out; int idx = i;
    if (idx < S0)              { in = w0; out = o0; }
    else if ((idx -= S0) < S1) { in = w1; out = o1; }
    else if ((idx -= S1) < S2) { in = w2; out = o2; }
    else {
        idx -= S2;
        if (idx >= S3) return;
        in = w3; out = o3;
    }
    int j  = idx & 15;
    int pj = ((j & 3) << 2) | (j >> 2);
    uint32_t v; CVT_TF32(v, in[idx]);
    ((uint32_t*)out)[(idx & ~15) | pj] = v;
}

// ---------------- LayerNorm -> tf32 + permuted output ----------------
__global__ __launch_bounds__(256) void ln_kernel(const float* __restrict__ x,
                                                 const float* __restrict__ w,
                                                 const float* __restrict__ b,
                                                 float* __restrict__ out)
{
    int row = blockIdx.x;
    const float* xr = x + (size_t)row * EMB;
    uint32_t* orow = (uint32_t*)(out + (size_t)row * EMB);
    int t = threadIdx.x;

    float v[3];
    float sum = 0.f, sq = 0.f;
#pragma unroll
    for (int i = 0; i < 3; i++) {
        v[i] = xr[t + 256 * i];
        sum += v[i];
        sq  += v[i] * v[i];
    }
    __shared__ float s1[8], s2[8], bc[2];
    for (int o = 16; o > 0; o >>= 1) {
        sum += __shfl_xor_sync(0xffffffffu, sum, o);
        sq  += __shfl_xor_sync(0xffffffffu, sq,  o);
    }
    int wid = t >> 5, lid = t & 31;
    if (lid == 0) { s1[wid] = sum; s2[wid] = sq; }
    __syncthreads();
    if (t == 0) {
        float ts = 0.f, tq = 0.f;
#pragma unroll
        for (int i = 0; i < 8; i++) { ts += s1[i]; tq += s2[i]; }
        float mu  = ts * (1.0f / EMB);
        float var = tq * (1.0f / EMB) - mu * mu;
        bc[0] = mu;
        bc[1] = rsqrtf(var + 1e-5f);
    }
    __syncthreads();
    float mu = bc[0], rstd = bc[1];
    int j  = t & 15;
    int pj = ((j & 3) << 2) | (j >> 2);
#pragma unroll
    for (int i = 0; i < 3; i++) {
        int c = t + 256 * i;
        float y = (v[i] - mu) * rstd * w[c] + b[c];
        uint32_t u; CVT_TF32(u, y);
        orow[(c & ~15) | pj] = u;
    }
}

// ---------------- cp.async tf32 GEMM (R9 config: k16 stages, GS=3) ----------------
#define GS 3
#define GBUF (128 * 16)
#define GT_SMEM (GS * 2 * GBUF * 4)         // 49152

template <int EPI>
__global__ __launch_bounds__(256, 2) void gemm_cp(
    const float* __restrict__ A, const float* __restrict__ B,
    const float* __restrict__ bias, const float* __restrict__ res,
    float* __restrict__ C, int M, int N, int K)
{
    extern __shared__ float smem[];
    const uint32_t sb = smem_u32(smem);

    const int tid  = threadIdx.x;
    const int wid  = tid >> 5;
    const int lane = tid & 31;
    const int g = lane >> 2, t = lane & 3;

    const int bm = blockIdx.y * 128;
    const int bn = blockIdx.x * 128;
    const int wm = (wid >> 2) * 64;
    const int wn = (wid & 3) * 32;

    const int lr = tid >> 1;
    const int hc = (tid & 1) * 2;
    const int sw = ((lr & 3) ^ ((lr >> 2) & 3)) << 2;
    const float* Ap = A + (size_t)(bm + lr) * K + hc * 4;
    const float* Bp = B + (size_t)(bn + lr) * K + hc * 4;
    const uint32_t dA0 = sb + (lr * 16 + ((4 * hc)     ^ sw)) * 4;
    const uint32_t dA1 = sb + (lr * 16 + ((4 * hc + 4) ^ sw)) * 4;
    const uint32_t dB0 = dA0 + GS * GBUF * 4;
    const uint32_t dB1 = dA1 + GS * GBUF * 4;

    const int cA0 = (4 * t) ^ (((g & 3) ^ ((g >> 2) & 3)) << 2);
    const int cA8 = (4 * t) ^ (((g & 3) ^ (((g >> 2) + 2) & 3)) << 2);
    int cB[4];
#pragma unroll
    for (int nt = 0; nt < 4; nt++)
        cB[nt] = (4 * t) ^ (((g & 3) ^ (((g >> 2) + 2 * nt) & 3)) << 2);

    float acc[4][4][4];
#pragma unroll
    for (int i = 0; i < 4; i++)
#pragma unroll
        for (int j = 0; j < 4; j++)
#pragma unroll
            for (int q = 0; q < 4; q++) acc[i][j][q] = 0.f;

    const int NC = K / 16;

#pragma unroll
    for (int c = 0; c < GS - 1; c++) {
        uint32_t so = (uint32_t)(c * GBUF * 4);
        const float* a = Ap + c * 16;
        const float* b = Bp + c * 16;
        cp16(dA0 + so, a);
        cp16(dA1 + so, a + 4);
        cp16(dB0 + so, b);
        cp16(dB1 + so, b + 4);
        CP_COMMIT();
    }

    for (int c = 0; c < NC; c++) {
        CP_WAIT(GS - 2);
        __syncthreads();

        int nc = c + GS - 1;
        if (nc < NC) {
            uint32_t so = (uint32_t)((nc % GS) * GBUF * 4);
            const float* a = Ap + nc * 16;
            const float* b = Bp + nc * 16;
            cp16(dA0 + so, a);
            cp16(dA1 + so, a + 4);
            cp16(dB0 + so, b);
            cp16(dB1 + so, b + 4);
        }
        CP_COMMIT();

        const int s = c % GS;
        const uint32_t* Ab = (const uint32_t*)(smem + s * GBUF);
        const uint32_t* Bb = (const uint32_t*)(smem + (GS + s) * GBUF);

        uint4 br[4];
#pragma unroll
        for (int nt = 0; nt < 4; nt++)
            br[nt] = *(const uint4*)&Bb[(wn + nt * 8 + g) * 16 + cB[nt]];

#pragma unroll
        for (int mt = 0; mt < 4; mt++) {
            const int r0 = wm + mt * 16 + g;
            uint4 ar0 = *(const uint4*)&Ab[r0 * 16 + cA0];
            uint4 ar1 = *(const uint4*)&Ab[(r0 + 8) * 16 + cA8];
#pragma unroll
            for (int nt = 0; nt < 4; nt++) {
                mma8v(acc[mt][nt], ar0.x, ar1.x, ar0.y, ar1.y, br[nt].x, br[nt].y);
                mma8v(acc[mt][nt], ar0.z, ar1.z, ar0.w, ar1.w, br[nt].z, br[nt].w);
            }
        }
    }

#pragma unroll
    for (int mt = 0; mt < 4; mt++) {
#pragma unroll
        for (int nt = 0; nt < 4; nt++) {
            int gcol = bn + wn + nt * 8 + 2 * t;
            float2 bv = *(const float2*)&bias[gcol];
            int r0 = bm + wm + mt * 16 + g;
#pragma unroll
            for (int hrow = 0; hrow < 2; hrow++) {
                int grow = r0 + hrow * 8;
                float c0 = acc[mt][nt][2 * hrow]     + bv.x;
                float c1 = acc[mt][nt][2 * hrow + 1] + bv.y;
                if (EPI == 1) {
                    size_t gidx = (size_t)grow * N + gcol;
                    float2 rv = *(const float2*)&res[gidx];
                    c0 += rv.x; c1 += rv.y;
                    *(float2*)&C[gidx] = make_float2(c0, c1);
                } else if (EPI == 0) {
                    size_t gidx = (size_t)grow * N + gcol;
                    *(float2*)&C[gidx] = make_float2(c0, c1);
                } else {
                    c0 = c0 / (1.f + __expf(-1.702f * c0));
                    c1 = c1 / (1.f + __expf(-1.702f * c1));
                    int p  = gcol & 15;
                    int pp = ((p & 3) << 2) | (p >> 2);
                    size_t b16 = (size_t)grow * N + (gcol & ~15);
                    uint32_t u0, u1;
                    CVT_TF32(u0, c0); CVT_TF32(u1, c1);
                    ((uint32_t*)C)[b16 + pp]     = u0;
                    ((uint32_t*)C)[b16 + pp + 4] = u1;
                }
            }
        }
    }
}

// ---------------- Flash attention: permuted K / transposed-permuted V ----------------
// Ks[kv 64][dh, stride 80], Vt[dh 64][kv, stride 80]: 16-block perm + XOR swizzle
// -> each k16 B-fragment is one LDS.128. Ps scratch unchanged.
#define AKS 80
#define PS_STR 68
#define ATT_SMEM ((64 * AKS + 64 * AKS + 4 * 16 * PS_STR) * 4)

__global__ __launch_bounds__(128) void attn_mma(const float* __restrict__ qkv,
                                                float* __restrict__ o)
{
    extern __shared__ float asmem[];
    float* Ks = asmem;                       // [64][AKS]
    float* Vt = asmem + 64 * AKS;            // [64][AKS]
    float* Ps = asmem + 2 * 64 * AKS;        // [4][16][PS_STR]

    const int tid  = threadIdx.x;
    const int w    = tid >> 5;
    const int lane = tid & 31;
    const int g = lane >> 2, t = lane & 3;
    const int qb = blockIdx.x * 64 + w * 16;
    const int h = blockIdx.y, n = blockIdx.z;

    const float qscale = 0.125f * 1.44269504088896f;

    uint32_t aq[8][4];
    {
        size_t r0 = ((size_t)(qb + g) * NB + n) * E3 + h * DH;
        size_t r1 = ((size_t)(qb + g + 8) * NB + n) * E3 + h * DH;
#pragma unroll
        for (int ch = 0; ch < 8; ch++) {
            float v0 = qkv[r0 + ch * 8 + t]     * qscale;
            float v1 = qkv[r1 + ch * 8 + t]     * qscale;
            float v2 = qkv[r0 + ch * 8 + t + 4] * qscale;
            float v3 = qkv[r1 + ch * 8 + t + 4] * qscale;
            CVT_TF32(aq[ch][0], v0); CVT_TF32(aq[ch][1], v1);
            CVT_TF32(aq[ch][2], v2); CVT_TF32(aq[ch][3], v3);
        }
    }

    float oc[8][4];
#pragma unroll
    for (int i = 0; i < 8; i++)
#pragma unroll
        for (int j = 0; j < 4; j++) oc[i][j] = 0.f;
    float m0 = -1e30f, m1 = -1e30f, l0 = 0.f, l1 = 0.f;

    const int srow  = tid >> 1;              // 0..63
    const int shalf = (tid & 1) * 32;        // 0 or 32
    const int swk   = swr(srow);             // K store swizzle (row = srow)
    const int pv    = (((srow & 3) << 2) | ((srow & 15) >> 2));  // perm(srow&15)
    const int vblk  = (srow >> 4) * 16;      // kv 16-block base for V store

    // fragment-read col offsets per nt (row r = nt*8+g)
    int fc[8];
#pragma unroll
    for (int nt = 0; nt < 8; nt++)
        fc[nt] = AKS * (nt * 8 + g) + ((4 * t) ^ swr(nt * 8 + g));

    for (int kb = 0; kb < L_SEQ / 64; kb++) {
        // ---- load K rows ----
        size_t kbase = ((size_t)(kb * 64 + srow) * NB + n) * E3 + EMB + h * DH + shalf;
        float4 kr[8];
#pragma unroll
        for (int i = 0; i < 8; i++) kr[i] = *(const float4*)&qkv[kbase + 4 * i];
        __syncthreads();   // prior tile fully consumed
        {
            uint32_t* ks = (uint32_t*)Ks;
            const float* kf = (const float*)kr;
#pragma unroll
            for (int i = 0; i < 32; i++) {
                int j  = shalf + i;
                int jj = j & 15;
                uint32_t u; CVT_TF32(u, kf[i]);
                ks[AKS * srow + (j & ~15) + ((((jj & 3) << 2) | (jj >> 2)) ^ swk)] = u;
            }
        }
        // ---- load V rows, store transposed ----
        size_t vbase = kbase + EMB;
#pragma unroll
        for (int i = 0; i < 8; i++) kr[i] = *(const float4*)&qkv[vbase + 4 * i];
        {
            uint32_t* vt = (uint32_t*)Vt;
            const float* vf = (const float*)kr;
#pragma unroll
            for (int i = 0; i < 32; i++) {
                int dh = shalf + i;
                uint32_t u; CVT_TF32(u, vf[i]);
                vt[AKS * dh + vblk + (pv ^ swr(dh))] = u;
            }
        }
        __syncthreads();

        // ---- S = Q K^T ----
        float sc[8][4];
#pragma unroll
        for (int i = 0; i < 8; i++)
#pragma unroll
            for (int j = 0; j < 4; j++) sc[i][j] = 0.f;

        const uint32_t* ksb = (const uint32_t*)Ks;
#pragma unroll
        for (int nt = 0; nt < 8; nt++) {
#pragma unroll
            for (int blk = 0; blk < 4; blk++) {
                uint4 kbv = *(const uint4*)&ksb[fc[nt] + 16 * blk];
                mma8v(sc[nt], aq[2*blk][0],   aq[2*blk][1],   aq[2*blk][2],   aq[2*blk][3],   kbv.x, kbv.y);
                mma8v(sc[nt], aq[2*blk+1][0], aq[2*blk+1][1], aq[2*blk+1][2], aq[2*blk+1][3], kbv.z, kbv.w);
            }
        }

        // ---- online softmax ----
        float tm0 = -1e30f, tm1 = -1e30f;
#pragma unroll
        for (int nt = 0; nt < 8; nt++) {
            tm0 = fmaxf(tm0, fmaxf(sc[nt][0], sc[nt][1]));
            tm1 = fmaxf(tm1, fmaxf(sc[nt][2], sc[nt][3]));
        }
        tm0 = fmaxf(tm0, __shfl_xor_sync(0xffffffffu, tm0, 1));
        tm0 = fmaxf(tm0, __shfl_xor_sync(0xffffffffu, tm0, 2));
        tm1 = fmaxf(tm1, __shfl_xor_sync(0xffffffffu, tm1, 1));
        tm1 = fmaxf(tm1, __shfl_xor_sync(0xffffffffu, tm1, 2));

        float nm0 = fmaxf(m0, tm0), nm1 = fmaxf(m1, tm1);
        float al0 = ex2f(m0 - nm0), al1 = ex2f(m1 - nm1);
        m0 = nm0; m1 = nm1;

        float s0 = 0.f, s1 = 0.f;
#pragma unroll
        for (int nt = 0; nt < 8; nt++) {
            sc[nt][0] = ex2f(sc[nt][0] - m0);
            sc[nt][1] = ex2f(sc[nt][1] - m0);
            sc[nt][2] = ex2f(sc[nt][2] - m1);
            sc[nt][3] = ex2f(sc[nt][3] - m1);
            s0 += sc[nt][0] + sc[nt][1];
            s1 += sc[nt][2] + sc[nt][3];
        }
        s0 += __shfl_xor_sync(0xffffffffu, s0, 1);
        s0 += __shfl_xor_sync(0xffffffffu, s0, 2);
        s1 += __shfl_xor_sync(0xffffffffu, s1, 1);
        s1 += __shfl_xor_sync(0xffffffffu, s1, 2);
        l0 = l0 * al0 + s0;
        l1 = l1 * al1 + s1;
#pragma unroll
        for (int nt = 0; nt < 8; nt++) {
            oc[nt][0] *= al0; oc[nt][1] *= al0;
            oc[nt][2] *= al1; oc[nt][3] *= al1;
        }

        // ---- stage P (per-warp scratch) ----
        uint32_t* pw = (uint32_t*)(Ps + w * 16 * PS_STR);
        __syncwarp();
#pragma unroll
        for (int nt = 0; nt < 8; nt++) {
            uint2 p0, p1;
            CVT_TF32(p0.x, sc[nt][0]); CVT_TF32(p0.y, sc[nt][1]);
            CVT_TF32(p1.x, sc[nt][2]); CVT_TF32(p1.y, sc[nt][3]);
            *(uint2*)&pw[g * PS_STR + nt * 8 + 2 * t]       = p0;
            *(uint2*)&pw[(g + 8) * PS_STR + nt * 8 + 2 * t] = p1;
        }
        __syncwarp();

        // ---- O += P V ----
        const uint32_t* vtb = (const uint32_t*)Vt;
#pragma unroll
        for (int blk = 0; blk < 4; blk++) {
            uint32_t a00 = pw[g * PS_STR + (2*blk) * 8 + t];
            uint32_t a01 = pw[(g + 8) * PS_STR + (2*blk) * 8 + t];
            uint32_t a02 = pw[g * PS_STR + (2*blk) * 8 + t + 4];
            uint32_t a03 = pw[(g + 8) * PS_STR + (2*blk) * 8 + t + 4];
            uint32_t a10 = pw[g * PS_STR + (2*blk+1) * 8 + t];
            uint32_t a11 = pw[(g + 8) * PS_STR + (2*blk+1) * 8 + t];
            uint32_t a12 = pw[g * PS_STR + (2*blk+1) * 8 + t + 4];
            uint32_t a13 = pw[(g + 8) * PS_STR + (2*blk+1) * 8 + t + 4];
#pragma unroll
            for (int nt = 0; nt < 8; nt++) {
                uint4 vb = *(const uint4*)&vtb[fc[nt] + 16 * blk];
                mma8v(oc[nt], a00, a01, a02, a03, vb.x, vb.y);
                mma8v(oc[nt], a10, a11, a12, a13, vb.z, vb.w);
            }
        }
    }

    // ---- epilogue: tf32 + permuted stores ----
    float i0 = 1.f / l0, i1 = 1.f / l1;
    size_t o0 = ((size_t)(qb + g) * NB + n) * EMB + h * DH;
    size_t o1 = ((size_t)(qb + g + 8) * NB + n) * EMB + h * DH;
#pragma unroll
    for (int nt = 0; nt < 8; nt++) {
        int d  = nt * 8 + 2 * t;
        int p  = d & 15;
        int pp = ((p & 3) << 2) | (p >> 2);
        int b16 = d & ~15;
        uint32_t u0, u1, u2, u3;
        CVT_TF32(u0, oc[nt][0] * i0); CVT_TF32(u1, oc[nt][1] * i0);
        CVT_TF32(u2, oc[nt][2] * i1); CVT_TF32(u3, oc[nt][3] * i1);
        ((uint32_t*)o)[o0 + b16 + pp]     = u0;
        ((uint32_t*)o)[o0 + b16 + pp + 4] = u1;
        ((uint32_t*)o)[o1 + b16 + pp]     = u2;
        ((uint32_t*)o)[o1 + b16 + pp + 4] = u3;
    }
}

// ---------------- launch ----------------
extern "C" void kernel_launch(void* const* d_in, const int* in_sizes, int n_in,
                              void* d_out, int out_size)
{
    const float* x      = (const float*)d_in[0];
    const float* ln1_w  = (const float*)d_in[1];
    const float* ln1_b  = (const float*)d_in[2];
    const float* w_qkv  = (const float*)d_in[3];
    const float* b_qkv  = (const float*)d_in[4];
    const float* w_out  = (const float*)d_in[5];
    const float* b_out  = (const float*)d_in[6];
    const float* ln2_w  = (const float*)d_in[7];
    const float* ln2_b  = (const float*)d_in[8];
    const float* w_fc   = (const float*)d_in[9];
    const float* b_fc   = (const float*)d_in[10];
    const float* w_proj = (const float*)d_in[11];
    const float* b_proj = (const float*)d_in[12];
    float* out = (float*)d_out;

    float *h, *qkv, *attn, *x1, *f, *wqkv, *wout, *wfc, *wproj;
    cudaGetSymbolAddress((void**)&h,     g_h);
    cudaGetSymbolAddress((void**)&qkv,   g_qkv);
    cudaGetSymbolAddress((void**)&attn,  g_attn);
    cudaGetSymbolAddress((void**)&x1,    g_x1);
    cudaGetSymbolAddress((void**)&f,     g_f);
    cudaGetSymbolAddress((void**)&wqkv,  g_wqkv);
    cudaGetSymbolAddress((void**)&wout,  g_wout);
    cudaGetSymbolAddress((void**)&wfc,   g_wfc);
    cudaGetSymbolAddress((void**)&wproj, g_wproj);

    cudaFuncSetAttribute(gemm_cp<0>, cudaFuncAttributeMaxDynamicSharedMemorySize, GT_SMEM);
    cudaFuncSetAttribute(gemm_cp<1>, cudaFuncAttributeMaxDynamicSharedMemorySize, GT_SMEM);
    cudaFuncSetAttribute(gemm_cp<2>, cudaFuncAttributeMaxDynamicSharedMemorySize, GT_SMEM);
    cudaFuncSetAttribute(attn_mma,   cudaFuncAttributeMaxDynamicSharedMemorySize, ATT_SMEM);

    int ptotal = S0 + S1 + S2 + S3;
    permute_all<<<(ptotal + 255) / 256, 256>>>(w_qkv, wqkv, w_out, wout,
                                               w_fc, wfc, w_proj, wproj);

    ln_kernel<<<ROWS, 256>>>(x, ln1_w, ln1_b, h);
    gemm_cp<0><<<dim3(E3 / 128, ROWS / 128), 256, GT_SMEM>>>(h, wqkv, b_qkv, nullptr, qkv,
                                                             ROWS, E3, EMB);
    attn_mma<<<dim3(L_SEQ / 64, NHEAD, NB), 128, ATT_SMEM>>>(qkv, attn);
    gemm_cp<1><<<dim3(EMB / 128, ROWS / 128), 256, GT_SMEM>>>(attn, wout, b_out, x, x1,
                                                              ROWS, EMB, EMB);
    ln_kernel<<<ROWS, 256>>>(x1, ln2_w, ln2_b, h);
    gemm_cp<2><<<dim3(E4 / 128, ROWS / 128), 256, GT_SMEM>>>(h, wfc, b_fc, nullptr, f,
                                                             ROWS, E4, EMB);
    gemm_cp<1><<<dim3(EMB / 128, ROWS / 128), 256, GT_SMEM>>>(f, wproj, b_proj, x1, out,
                                                              ROWS, EMB, E4);
}

// round 12
// speedup vs baseline: 1.2671x; 1.1824x over previous
#include <cuda_runtime.h>
#include <math.h>
#include <stdint.h>

#define L_SEQ  2048
#define NB     4
#define EMB    768
#define NHEAD  12
#define DH     64
#define ROWS   (L_SEQ * NB)      // 8192
#define E3     (3 * EMB)         // 2304
#define E4     (4 * EMB)         // 3072

// ---------------- scratch ----------------
__device__ float g_h   [ (size_t)ROWS * EMB ];
__device__ float g_qkv [ (size_t)ROWS * E3  ];
__device__ float g_attn[ (size_t)ROWS * EMB ];
__device__ float g_x1  [ (size_t)ROWS * EMB ];
__device__ float g_f   [ (size_t)ROWS * E4  ];
__device__ float g_wqkv [ (size_t)E3  * EMB ];
__device__ float g_wout [ (size_t)EMB * EMB ];
__device__ float g_wfc  [ (size_t)E4  * EMB ];
__device__ float g_wproj[ (size_t)EMB * E4  ];

#define CVT_TF32(d, s) asm volatile("cvt.rna.tf32.f32 %0, %1;" : "=r"(d) : "f"(s))
// d = {lo, hi} packed bf16x2 (lo = lower k index)
#define PACK_BF16X2(d, lo, hi) \
    asm volatile("cvt.rn.bf16x2.f32 %0, %1, %2;" : "=r"(d) : "f"(hi), "f"(lo))

__device__ __forceinline__ uint32_t smem_u32(const void* p) {
    uint32_t a;
    asm("{ .reg .u64 t; cvta.to.shared.u64 t, %1; cvt.u32.u64 %0, t; }" : "=r"(a) : "l"(p));
    return a;
}
__device__ __forceinline__ void cp16(uint32_t dst, const void* src) {
    asm volatile("cp.async.cg.shared.global [%0], [%1], 16;" :: "r"(dst), "l"(src));
}
#define CP_COMMIT() asm volatile("cp.async.commit_group;" ::: "memory")
#define CP_WAIT(n)  asm volatile("cp.async.wait_group %0;" :: "n"(n) : "memory")

__device__ __forceinline__ float ex2f(float x) {
    float y; asm("ex2.approx.f32 %0, %1;" : "=f"(y) : "f"(x)); return y;
}
__device__ __forceinline__ void mma8v(float* c,
                                      uint32_t a0, uint32_t a1, uint32_t a2, uint32_t a3,
                                      uint32_t b0, uint32_t b1) {
    asm volatile(
        "mma.sync.aligned.m16n8k8.row.col.f32.tf32.tf32.f32 "
        "{%0,%1,%2,%3}, {%4,%5,%6,%7}, {%8,%9}, {%0,%1,%2,%3};"
        : "+f"(c[0]), "+f"(c[1]), "+f"(c[2]), "+f"(c[3])
        : "r"(a0), "r"(a1), "r"(a2), "r"(a3), "r"(b0), "r"(b1));
}
__device__ __forceinline__ void mma16bf(float* c,
                                        uint32_t a0, uint32_t a1, uint32_t a2, uint32_t a3,
                                        uint32_t b0, uint32_t b1) {
    asm volatile(
        "mma.sync.aligned.m16n8k16.row.col.f32.bf16.bf16.f32 "
        "{%0,%1,%2,%3}, {%4,%5,%6,%7}, {%8,%9}, {%0,%1,%2,%3};"
        : "+f"(c[0]), "+f"(c[1]), "+f"(c[2]), "+f"(c[3])
        : "r"(a0), "r"(a1), "r"(a2), "r"(a3), "r"(b0), "r"(b1));
}

// ---------------- merged weight permute + tf32 round ----------------
#define S0 (E3 * EMB)
#define S1 (EMB * EMB)
#define S2 (E4 * EMB)
#define S3 (EMB * E4)
__global__ __launch_bounds__(256) void permute_all(
    const float* __restrict__ w0, float* __restrict__ o0,
    const float* __restrict__ w1, float* __restrict__ o1,
    const float* __restrict__ w2, float* __restrict__ o2,
    const float* __restrict__ w3, float* __restrict__ o3)
{
    int i = blockIdx.x * 256 + threadIdx.x;
    const float* in; float* out; int idx = i;
    if (idx < S0)              { in = w0; out = o0; }
    else if ((idx -= S0) < S1) { in = w1; out = o1; }
    else if ((idx -= S1) < S2) { in = w2; out = o2; }
    else {
        idx -= S2;
        if (idx >= S3) return;
        in = w3; out = o3;
    }
    int j  = idx & 15;
    int pj = ((j & 3) << 2) | (j >> 2);
    uint32_t v; CVT_TF32(v, in[idx]);
    ((uint32_t*)out)[(idx & ~15) | pj] = v;
}

// ---------------- LayerNorm -> tf32 + permuted output ----------------
__global__ __launch_bounds__(256) void ln_kernel(const float* __restrict__ x,
                                                 const float* __restrict__ w,
                                                 const float* __restrict__ b,
                                                 float* __restrict__ out)
{
    int row = blockIdx.x;
    const float* xr = x + (size_t)row * EMB;
    uint32_t* orow = (uint32_t*)(out + (size_t)row * EMB);
    int t = threadIdx.x;

    float v[3];
    float sum = 0.f, sq = 0.f;
#pragma unroll
    for (int i = 0; i < 3; i++) {
        v[i] = xr[t + 256 * i];
        sum += v[i];
        sq  += v[i] * v[i];
    }
    __shared__ float s1[8], s2[8], bc[2];
    for (int o = 16; o > 0; o >>= 1) {
        sum += __shfl_xor_sync(0xffffffffu, sum, o);
        sq  += __shfl_xor_sync(0xffffffffu, sq,  o);
    }
    int wid = t >> 5, lid = t & 31;
    if (lid == 0) { s1[wid] = sum; s2[wid] = sq; }
    __syncthreads();
    if (t == 0) {
        float ts = 0.f, tq = 0.f;
#pragma unroll
        for (int i = 0; i < 8; i++) { ts += s1[i]; tq += s2[i]; }
        float mu  = ts * (1.0f / EMB);
        float var = tq * (1.0f / EMB) - mu * mu;
        bc[0] = mu;
        bc[1] = rsqrtf(var + 1e-5f);
    }
    __syncthreads();
    float mu = bc[0], rstd = bc[1];
    int j  = t & 15;
    int pj = ((j & 3) << 2) | (j >> 2);
#pragma unroll
    for (int i = 0; i < 3; i++) {
        int c = t + 256 * i;
        float y = (v[i] - mu) * rstd * w[c] + b[c];
        uint32_t u; CVT_TF32(u, y);
        orow[(c & ~15) | pj] = u;
    }
}

// ---------------- cp.async tf32 GEMM (R9 config: k16 stages, GS=3) ----------------
#define GS 3
#define GBUF (128 * 16)
#define GT_SMEM (GS * 2 * GBUF * 4)         // 49152

template <int EPI>
__global__ __launch_bounds__(256, 2) void gemm_cp(
    const float* __restrict__ A, const float* __restrict__ B,
    const float* __restrict__ bias, const float* __restrict__ res,
    float* __restrict__ C, int M, int N, int K)
{
    extern __shared__ float smem[];
    const uint32_t sb = smem_u32(smem);

    const int tid  = threadIdx.x;
    const int wid  = tid >> 5;
    const int lane = tid & 31;
    const int g = lane >> 2, t = lane & 3;

    const int bm = blockIdx.y * 128;
    const int bn = blockIdx.x * 128;
    const int wm = (wid >> 2) * 64;
    const int wn = (wid & 3) * 32;

    const int lr = tid >> 1;
    const int hc = (tid & 1) * 2;
    const int sw = ((lr & 3) ^ ((lr >> 2) & 3)) << 2;
    const float* Ap = A + (size_t)(bm + lr) * K + hc * 4;
    const float* Bp = B + (size_t)(bn + lr) * K + hc * 4;
    const uint32_t dA0 = sb + (lr * 16 + ((4 * hc)     ^ sw)) * 4;
    const uint32_t dA1 = sb + (lr * 16 + ((4 * hc + 4) ^ sw)) * 4;
    const uint32_t dB0 = dA0 + GS * GBUF * 4;
    const uint32_t dB1 = dA1 + GS * GBUF * 4;

    const int cA0 = (4 * t) ^ (((g & 3) ^ ((g >> 2) & 3)) << 2);
    const int cA8 = (4 * t) ^ (((g & 3) ^ (((g >> 2) + 2) & 3)) << 2);
    int cB[4];
#pragma unroll
    for (int nt = 0; nt < 4; nt++)
        cB[nt] = (4 * t) ^ (((g & 3) ^ (((g >> 2) + 2 * nt) & 3)) << 2);

    float acc[4][4][4];
#pragma unroll
    for (int i = 0; i < 4; i++)
#pragma unroll
        for (int j = 0; j < 4; j++)
#pragma unroll
            for (int q = 0; q < 4; q++) acc[i][j][q] = 0.f;

    const int NC = K / 16;

#pragma unroll
    for (int c = 0; c < GS - 1; c++) {
        uint32_t so = (uint32_t)(c * GBUF * 4);
        const float* a = Ap + c * 16;
        const float* b = Bp + c * 16;
        cp16(dA0 + so, a);
        cp16(dA1 + so, a + 4);
        cp16(dB0 + so, b);
        cp16(dB1 + so, b + 4);
        CP_COMMIT();
    }

    for (int c = 0; c < NC; c++) {
        CP_WAIT(GS - 2);
        __syncthreads();

        int nc = c + GS - 1;
        if (nc < NC) {
            uint32_t so = (uint32_t)((nc % GS) * GBUF * 4);
            const float* a = Ap + nc * 16;
            const float* b = Bp + nc * 16;
            cp16(dA0 + so, a);
            cp16(dA1 + so, a + 4);
            cp16(dB0 + so, b);
            cp16(dB1 + so, b + 4);
        }
        CP_COMMIT();

        const int s = c % GS;
        const uint32_t* Ab = (const uint32_t*)(smem + s * GBUF);
        const uint32_t* Bb = (const uint32_t*)(smem + (GS + s) * GBUF);

        uint4 br[4];
#pragma unroll
        for (int nt = 0; nt < 4; nt++)
            br[nt] = *(const uint4*)&Bb[(wn + nt * 8 + g) * 16 + cB[nt]];

#pragma unroll
        for (int mt = 0; mt < 4; mt++) {
            const int r0 = wm + mt * 16 + g;
            uint4 ar0 = *(const uint4*)&Ab[r0 * 16 + cA0];
            uint4 ar1 = *(const uint4*)&Ab[(r0 + 8) * 16 + cA8];
#pragma unroll
            for (int nt = 0; nt < 4; nt++) {
                mma8v(acc[mt][nt], ar0.x, ar1.x, ar0.y, ar1.y, br[nt].x, br[nt].y);
                mma8v(acc[mt][nt], ar0.z, ar1.z, ar0.w, ar1.w, br[nt].z, br[nt].w);
            }
        }
    }

#pragma unroll
    for (int mt = 0; mt < 4; mt++) {
#pragma unroll
        for (int nt = 0; nt < 4; nt++) {
            int gcol = bn + wn + nt * 8 + 2 * t;
            float2 bv = *(const float2*)&bias[gcol];
            int r0 = bm + wm + mt * 16 + g;
#pragma unroll
            for (int hrow = 0; hrow < 2; hrow++) {
                int grow = r0 + hrow * 8;
                float c0 = acc[mt][nt][2 * hrow]     + bv.x;
                float c1 = acc[mt][nt][2 * hrow + 1] + bv.y;
                if (EPI == 1) {
                    size_t gidx = (size_t)grow * N + gcol;
                    float2 rv = *(const float2*)&res[gidx];
                    c0 += rv.x; c1 += rv.y;
                    *(float2*)&C[gidx] = make_float2(c0, c1);
                } else if (EPI == 0) {
                    size_t gidx = (size_t)grow * N + gcol;
                    *(float2*)&C[gidx] = make_float2(c0, c1);
                } else {
                    c0 = c0 / (1.f + __expf(-1.702f * c0));
                    c1 = c1 / (1.f + __expf(-1.702f * c1));
                    int p  = gcol & 15;
                    int pp = ((p & 3) << 2) | (p >> 2);
                    size_t b16 = (size_t)grow * N + (gcol & ~15);
                    uint32_t u0, u1;
                    CVT_TF32(u0, c0); CVT_TF32(u1, c1);
                    ((uint32_t*)C)[b16 + pp]     = u0;
                    ((uint32_t*)C)[b16 + pp + 4] = u1;
                }
            }
        }
    }
}

// ---------------- Flash attention: tf32 QK^T + bf16 P·V (P in registers) ----------------
// Ks[64][68] tf32 (R10 layout). Vp[32][72] uint32: word (r, d) = bf16x2{V[2r][d], V[2r+1][d]}.
#define KS_STR 68
#define VP_STR 72
#define ATT_SMEM ((64 * KS_STR + 32 * VP_STR) * 4)   // 26624 B

__global__ __launch_bounds__(128) void attn_mma(const float* __restrict__ qkv,
                                                float* __restrict__ o)
{
    extern __shared__ float asmem[];
    float*    Ks = asmem;                            // [64][KS_STR]
    uint32_t* Vp = (uint32_t*)(asmem + 64 * KS_STR); // [32][VP_STR]

    const int tid  = threadIdx.x;
    const int lane = tid & 31;
    const int w    = tid >> 5;
    const int g = lane >> 2, t = lane & 3;
    const int qb = blockIdx.x * 64 + w * 16;
    const int h = blockIdx.y, n = blockIdx.z;

    const float qscale = 0.125f * 1.44269504088896f;

    uint32_t aq[8][4];
    {
        size_t r0 = ((size_t)(qb + g) * NB + n) * E3 + h * DH;
        size_t r1 = ((size_t)(qb + g + 8) * NB + n) * E3 + h * DH;
#pragma unroll
        for (int ch = 0; ch < 8; ch++) {
            float v0 = qkv[r0 + ch * 8 + t]     * qscale;
            float v1 = qkv[r1 + ch * 8 + t]     * qscale;
            float v2 = qkv[r0 + ch * 8 + t + 4] * qscale;
            float v3 = qkv[r1 + ch * 8 + t + 4] * qscale;
            CVT_TF32(aq[ch][0], v0); CVT_TF32(aq[ch][1], v1);
            CVT_TF32(aq[ch][2], v2); CVT_TF32(aq[ch][3], v3);
        }
    }

    float oc[8][4];
#pragma unroll
    for (int i = 0; i < 8; i++)
#pragma unroll
        for (int j = 0; j < 4; j++) oc[i][j] = 0.f;
    float m0 = -1e30f, m1 = -1e30f, l0 = 0.f, l1 = 0.f;

    // K staging map (R10): thread -> (row srow, half shalf)
    const int srow  = tid >> 1;
    const int shalf = (tid & 1) * 32;
    // V staging map: thread -> (pair r, quarter q)
    const int vr = tid >> 2;            // 0..31
    const int vq = (tid & 3) * 16;      // dh base

    for (int kb = 0; kb < L_SEQ / 64; kb++) {
        // ---- load K rows to regs ----
        size_t kbase = ((size_t)(kb * 64 + srow) * NB + n) * E3 + EMB + h * DH + shalf;
        float4 kr[8];
#pragma unroll
        for (int i = 0; i < 8; i++) kr[i] = *(const float4*)&qkv[kbase + 4 * i];
        // ---- load V row pair to regs ----
        size_t vb0 = ((size_t)(kb * 64 + 2 * vr)     * NB + n) * E3 + 2 * EMB + h * DH + vq;
        size_t vb1 = ((size_t)(kb * 64 + 2 * vr + 1) * NB + n) * E3 + 2 * EMB + h * DH + vq;
        float4 vr0[4], vr1[4];
#pragma unroll
        for (int i = 0; i < 4; i++) {
            vr0[i] = *(const float4*)&qkv[vb0 + 4 * i];
            vr1[i] = *(const float4*)&qkv[vb1 + 4 * i];
        }
        __syncthreads();   // prior tile fully consumed
        // ---- store K (tf32) ----
        {
            uint32_t* ks = (uint32_t*)&Ks[srow * KS_STR + shalf];
#pragma unroll
            for (int i = 0; i < 8; i++) {
                uint4 cv;
                CVT_TF32(cv.x, kr[i].x); CVT_TF32(cv.y, kr[i].y);
                CVT_TF32(cv.z, kr[i].z); CVT_TF32(cv.w, kr[i].w);
                *(uint4*)&ks[4 * i] = cv;
            }
        }
        // ---- store V (bf16x2 pairs) ----
        {
            const float* f0 = (const float*)vr0;
            const float* f1 = (const float*)vr1;
            uint32_t* vp = &Vp[vr * VP_STR + vq];
#pragma unroll
            for (int i = 0; i < 4; i++) {
                uint4 cv;
                PACK_BF16X2(cv.x, f0[4*i],   f1[4*i]);
                PACK_BF16X2(cv.y, f0[4*i+1], f1[4*i+1]);
                PACK_BF16X2(cv.z, f0[4*i+2], f1[4*i+2]);
                PACK_BF16X2(cv.w, f0[4*i+3], f1[4*i+3]);
                *(uint4*)&vp[4 * i] = cv;
            }
        }
        __syncthreads();

        // ---- S = Q K^T (tf32) ----
        float sc[8][4];
#pragma unroll
        for (int i = 0; i < 8; i++)
#pragma unroll
            for (int j = 0; j < 4; j++) sc[i][j] = 0.f;

        const uint32_t* ksb = (const uint32_t*)Ks;
#pragma unroll
        for (int nt = 0; nt < 8; nt++) {
#pragma unroll
            for (int ch = 0; ch < 8; ch++) {
                uint32_t b0 = ksb[(nt * 8 + g) * KS_STR + ch * 8 + t];
                uint32_t b1 = ksb[(nt * 8 + g) * KS_STR + ch * 8 + t + 4];
                mma8v(sc[nt], aq[ch][0], aq[ch][1], aq[ch][2], aq[ch][3], b0, b1);
            }
        }

        // ---- online softmax ----
        float tm0 = -1e30f, tm1 = -1e30f;
#pragma unroll
        for (int nt = 0; nt < 8; nt++) {
            tm0 = fmaxf(tm0, fmaxf(sc[nt][0], sc[nt][1]));
            tm1 = fmaxf(tm1, fmaxf(sc[nt][2], sc[nt][3]));
        }
        tm0 = fmaxf(tm0, __shfl_xor_sync(0xffffffffu, tm0, 1));
        tm0 = fmaxf(tm0, __shfl_xor_sync(0xffffffffu, tm0, 2));
        tm1 = fmaxf(tm1, __shfl_xor_sync(0xffffffffu, tm1, 1));
        tm1 = fmaxf(tm1, __shfl_xor_sync(0xffffffffu, tm1, 2));

        float nm0 = fmaxf(m0, tm0), nm1 = fmaxf(m1, tm1);
        float al0 = ex2f(m0 - nm0), al1 = ex2f(m1 - nm1);
        m0 = nm0; m1 = nm1;

        float s0 = 0.f, s1 = 0.f;
#pragma unroll
        for (int nt = 0; nt < 8; nt++) {
            sc[nt][0] = ex2f(sc[nt][0] - m0);
            sc[nt][1] = ex2f(sc[nt][1] - m0);
            sc[nt][2] = ex2f(sc[nt][2] - m1);
            sc[nt][3] = ex2f(sc[nt][3] - m1);
            s0 += sc[nt][0] + sc[nt][1];
            s1 += sc[nt][2] + sc[nt][3];
        }
        s0 += __shfl_xor_sync(0xffffffffu, s0, 1);
        s0 += __shfl_xor_sync(0xffffffffu, s0, 2);
        s1 += __shfl_xor_sync(0xffffffffu, s1, 1);
        s1 += __shfl_xor_sync(0xffffffffu, s1, 2);
        l0 = l0 * al0 + s0;
        l1 = l1 * al1 + s1;
#pragma unroll
        for (int nt = 0; nt < 8; nt++) {
            oc[nt][0] *= al0; oc[nt][1] *= al0;
            oc[nt][2] *= al1; oc[nt][3] *= al1;
        }

        // ---- O += P V  (bf16, P direct from C fragments) ----
#pragma unroll
        for (int kk = 0; kk < 4; kk++) {
            uint32_t a0, a1, a2, a3;
            PACK_BF16X2(a0, sc[2*kk][0],   sc[2*kk][1]);
            PACK_BF16X2(a1, sc[2*kk][2],   sc[2*kk][3]);
            PACK_BF16X2(a2, sc[2*kk+1][0], sc[2*kk+1][1]);
            PACK_BF16X2(a3, sc[2*kk+1][2], sc[2*kk+1][3]);
#pragma unroll
            for (int nt = 0; nt < 8; nt++) {
                uint32_t b0 = Vp[(8 * kk + t)     * VP_STR + nt * 8 + g];
                uint32_t b1 = Vp[(8 * kk + t + 4) * VP_STR + nt * 8 + g];
                mma16bf(oc[nt], a0, a1, a2, a3, b0, b1);
            }
        }
    }

    // ---- epilogue: tf32 + permuted stores ----
    float i0 = 1.f / l0, i1 = 1.f / l1;
    size_t o0 = ((size_t)(qb + g) * NB + n) * EMB + h * DH;
    size_t o1 = ((size_t)(qb + g + 8) * NB + n) * EMB + h * DH;
#pragma unroll
    for (int nt = 0; nt < 8; nt++) {
        int d  = nt * 8 + 2 * t;
        int p  = d & 15;
        int pp = ((p & 3) << 2) | (p >> 2);
        int b16 = d & ~15;
        uint32_t u0, u1, u2, u3;
        CVT_TF32(u0, oc[nt][0] * i0); CVT_TF32(u1, oc[nt][1] * i0);
        CVT_TF32(u2, oc[nt][2] * i1); CVT_TF32(u3, oc[nt][3] * i1);
        ((uint32_t*)o)[o0 + b16 + pp]     = u0;
        ((uint32_t*)o)[o0 + b16 + pp + 4] = u1;
        ((uint32_t*)o)[o1 + b16 + pp]     = u2;
        ((uint32_t*)o)[o1 + b16 + pp + 4] = u3;
    }
}

// ---------------- launch ----------------
extern "C" void kernel_launch(void* const* d_in, const int* in_sizes, int n_in,
                              void* d_out, int out_size)
{
    const float* x      = (const float*)d_in[0];
    const float* ln1_w  = (const float*)d_in[1];
    const float* ln1_b  = (const float*)d_in[2];
    const float* w_qkv  = (const float*)d_in[3];
    const float* b_qkv  = (const float*)d_in[4];
    const float* w_out  = (const float*)d_in[5];
    const float* b_out  = (const float*)d_in[6];
    const float* ln2_w  = (const float*)d_in[7];
    const float* ln2_b  = (const float*)d_in[8];
    const float* w_fc   = (const float*)d_in[9];
    const float* b_fc   = (const float*)d_in[10];
    const float* w_proj = (const float*)d_in[11];
    const float* b_proj = (const float*)d_in[12];
    float* out = (float*)d_out;

    float *h, *qkv, *attn, *x1, *f, *wqkv, *wout, *wfc, *wproj;
    cudaGetSymbolAddress((void**)&h,     g_h);
    cudaGetSymbolAddress((void**)&qkv,   g_qkv);
    cudaGetSymbolAddress((void**)&attn,  g_attn);
    cudaGetSymbolAddress((void**)&x1,    g_x1);
    cudaGetSymbolAddress((void**)&f,     g_f);
    cudaGetSymbolAddress((void**)&wqkv,  g_wqkv);
    cudaGetSymbolAddress((void**)&wout,  g_wout);
    cudaGetSymbolAddress((void**)&wfc,   g_wfc);
    cudaGetSymbolAddress((void**)&wproj, g_wproj);

    cudaFuncSetAttribute(gemm_cp<0>, cudaFuncAttributeMaxDynamicSharedMemorySize, GT_SMEM);
    cudaFuncSetAttribute(gemm_cp<1>, cudaFuncAttributeMaxDynamicSharedMemorySize, GT_SMEM);
    cudaFuncSetAttribute(gemm_cp<2>, cudaFuncAttributeMaxDynamicSharedMemorySize, GT_SMEM);
    cudaFuncSetAttribute(attn_mma,   cudaFuncAttributeMaxDynamicSharedMemorySize, ATT_SMEM);

    int ptotal = S0 + S1 + S2 + S3;
    permute_all<<<(ptotal + 255) / 256, 256>>>(w_qkv, wqkv, w_out, wout,
                                               w_fc, wfc, w_proj, wproj);

    ln_kernel<<<ROWS, 256>>>(x, ln1_w, ln1_b, h);
    gemm_cp<0><<<dim3(E3 / 128, ROWS / 128), 256, GT_SMEM>>>(h, wqkv, b_qkv, nullptr, qkv,
                                                             ROWS, E3, EMB);
    attn_mma<<<dim3(L_SEQ / 64, NHEAD, NB), 128, ATT_SMEM>>>(qkv, attn);
    gemm_cp<1><<<dim3(EMB / 128, ROWS / 128), 256, GT_SMEM>>>(attn, wout, b_out, x, x1,
                                                              ROWS, EMB, EMB);
    ln_kernel<<<ROWS, 256>>>(x1, ln2_w, ln2_b, h);
    gemm_cp<2><<<dim3(E4 / 128, ROWS / 128), 256, GT_SMEM>>>(h, wfc, b_fc, nullptr, f,
                                                             ROWS, E4, EMB);
    gemm_cp<1><<<dim3(EMB / 128, ROWS / 128), 256, GT_SMEM>>>(f, wproj, b_proj, x1, out,
                                                              ROWS, EMB, E4);
}

// round 13
// speedup vs baseline: 1.3369x; 1.0551x over previous
#include <cuda_runtime.h>
#include <math.h>
#include <stdint.h>

#define L_SEQ  2048
#define NB     4
#define EMB    768
#define NHEAD  12
#define DH     64
#define ROWS   (L_SEQ * NB)      // 8192
#define E3     (3 * EMB)         // 2304
#define E4     (4 * EMB)         // 3072

// ---------------- scratch ----------------
__device__ float g_h   [ (size_t)ROWS * EMB ];
__device__ float g_qkv [ (size_t)ROWS * E3  ];   // tf32 + k-permuted (EPI=3 producer)
__device__ float g_attn[ (size_t)ROWS * EMB ];   // tf32 + k-permuted
__device__ float g_x1  [ (size_t)ROWS * EMB ];
__device__ float g_f   [ (size_t)ROWS * E4  ];
__device__ float g_wqkv [ (size_t)E3  * EMB ];
__device__ float g_wout [ (size_t)EMB * EMB ];
__device__ float g_wfc  [ (size_t)E4  * EMB ];
__device__ float g_wproj[ (size_t)EMB * E4  ];

#define CVT_TF32(d, s) asm volatile("cvt.rna.tf32.f32 %0, %1;" : "=r"(d) : "f"(s))
#define PACK_BF16X2(d, lo, hi) \
    asm volatile("cvt.rn.bf16x2.f32 %0, %1, %2;" : "=r"(d) : "f"(hi), "f"(lo))

__device__ __forceinline__ uint32_t smem_u32(const void* p) {
    uint32_t a;
    asm("{ .reg .u64 t; cvta.to.shared.u64 t, %1; cvt.u32.u64 %0, t; }" : "=r"(a) : "l"(p));
    return a;
}
__device__ __forceinline__ void cp16(uint32_t dst, const void* src) {
    asm volatile("cp.async.cg.shared.global [%0], [%1], 16;" :: "r"(dst), "l"(src));
}
#define CP_COMMIT() asm volatile("cp.async.commit_group;" ::: "memory")
#define CP_WAIT(n)  asm volatile("cp.async.wait_group %0;" :: "n"(n) : "memory")

__device__ __forceinline__ float ex2f(float x) {
    float y; asm("ex2.approx.f32 %0, %1;" : "=f"(y) : "f"(x)); return y;
}
__device__ __forceinline__ void mma8v(float* c,
                                      uint32_t a0, uint32_t a1, uint32_t a2, uint32_t a3,
                                      uint32_t b0, uint32_t b1) {
    asm volatile(
        "mma.sync.aligned.m16n8k8.row.col.f32.tf32.tf32.f32 "
        "{%0,%1,%2,%3}, {%4,%5,%6,%7}, {%8,%9}, {%0,%1,%2,%3};"
        : "+f"(c[0]), "+f"(c[1]), "+f"(c[2]), "+f"(c[3])
        : "r"(a0), "r"(a1), "r"(a2), "r"(a3), "r"(b0), "r"(b1));
}
__device__ __forceinline__ void mma16bf(float* c,
                                        uint32_t a0, uint32_t a1, uint32_t a2, uint32_t a3,
                                        uint32_t b0, uint32_t b1) {
    asm volatile(
        "mma.sync.aligned.m16n8k16.row.col.f32.bf16.bf16.f32 "
        "{%0,%1,%2,%3}, {%4,%5,%6,%7}, {%8,%9}, {%0,%1,%2,%3};"
        : "+f"(c[0]), "+f"(c[1]), "+f"(c[2]), "+f"(c[3])
        : "r"(a0), "r"(a1), "r"(a2), "r"(a3), "r"(b0), "r"(b1));
}

// ---------------- merged weight permute + tf32 round ----------------
#define S0 (E3 * EMB)
#define S1 (EMB * EMB)
#define S2 (E4 * EMB)
#define S3 (EMB * E4)
__global__ __launch_bounds__(256) void permute_all(
    const float* __restrict__ w0, float* __restrict__ o0,
    const float* __restrict__ w1, float* __restrict__ o1,
    const float* __restrict__ w2, float* __restrict__ o2,
    const float* __restrict__ w3, float* __restrict__ o3)
{
    int i = blockIdx.x * 256 + threadIdx.x;
    const float* in; float* out; int idx = i;
    if (idx < S0)              { in = w0; out = o0; }
    else if ((idx -= S0) < S1) { in = w1; out = o1; }
    else if ((idx -= S1) < S2) { in = w2; out = o2; }
    else {
        idx -= S2;
        if (idx >= S3) return;
        in = w3; out = o3;
    }
    int j  = idx & 15;
    int pj = ((j & 3) << 2) | (j >> 2);
    uint32_t v; CVT_TF32(v, in[idx]);
    ((uint32_t*)out)[(idx & ~15) | pj] = v;
}

// ---------------- LayerNorm -> tf32 + permuted output ----------------
__global__ __launch_bounds__(256) void ln_kernel(const float* __restrict__ x,
                                                 const float* __restrict__ w,
                                                 const float* __restrict__ b,
                                                 float* __restrict__ out)
{
    int row = blockIdx.x;
    const float* xr = x + (size_t)row * EMB;
    uint32_t* orow = (uint32_t*)(out + (size_t)row * EMB);
    int t = threadIdx.x;

    float v[3];
    float sum = 0.f, sq = 0.f;
#pragma unroll
    for (int i = 0; i < 3; i++) {
        v[i] = xr[t + 256 * i];
        sum += v[i];
        sq  += v[i] * v[i];
    }
    __shared__ float s1[8], s2[8], bc[2];
    for (int o = 16; o > 0; o >>= 1) {
        sum += __shfl_xor_sync(0xffffffffu, sum, o);
        sq  += __shfl_xor_sync(0xffffffffu, sq,  o);
    }
    int wid = t >> 5, lid = t & 31;
    if (lid == 0) { s1[wid] = sum; s2[wid] = sq; }
    __syncthreads();
    if (t == 0) {
        float ts = 0.f, tq = 0.f;
#pragma unroll
        for (int i = 0; i < 8; i++) { ts += s1[i]; tq += s2[i]; }
        float mu  = ts * (1.0f / EMB);
        float var = tq * (1.0f / EMB) - mu * mu;
        bc[0] = mu;
        bc[1] = rsqrtf(var + 1e-5f);
    }
    __syncthreads();
    float mu = bc[0], rstd = bc[1];
    int j  = t & 15;
    int pj = ((j & 3) << 2) | (j >> 2);
#pragma unroll
    for (int i = 0; i < 3; i++) {
        int c = t + 256 * i;
        float y = (v[i] - mu) * rstd * w[c] + b[c];
        uint32_t u; CVT_TF32(u, y);
        orow[(c & ~15) | pj] = u;
    }
}

// ---------------- cp.async tf32 GEMM (k16 stages, GS=3) ----------------
// EPI 0: plain  1: +res  2: QuickGELU+permuted  3: plain+permuted
#define GS 3
#define GBUF (128 * 16)
#define GT_SMEM (GS * 2 * GBUF * 4)         // 49152

template <int EPI>
__global__ __launch_bounds__(256, 2) void gemm_cp(
    const float* __restrict__ A, const float* __restrict__ B,
    const float* __restrict__ bias, const float* __restrict__ res,
    float* __restrict__ C, int M, int N, int K)
{
    extern __shared__ float smem[];
    const uint32_t sb = smem_u32(smem);

    const int tid  = threadIdx.x;
    const int wid  = tid >> 5;
    const int lane = tid & 31;
    const int g = lane >> 2, t = lane & 3;

    const int bm = blockIdx.y * 128;
    const int bn = blockIdx.x * 128;
    const int wm = (wid >> 2) * 64;
    const int wn = (wid & 3) * 32;

    const int lr = tid >> 1;
    const int hc = (tid & 1) * 2;
    const int sw = ((lr & 3) ^ ((lr >> 2) & 3)) << 2;
    const float* Ap = A + (size_t)(bm + lr) * K + hc * 4;
    const float* Bp = B + (size_t)(bn + lr) * K + hc * 4;
    const uint32_t dA0 = sb + (lr * 16 + ((4 * hc)     ^ sw)) * 4;
    const uint32_t dA1 = sb + (lr * 16 + ((4 * hc + 4) ^ sw)) * 4;
    const uint32_t dB0 = dA0 + GS * GBUF * 4;
    const uint32_t dB1 = dA1 + GS * GBUF * 4;

    const int cA0 = (4 * t) ^ (((g & 3) ^ ((g >> 2) & 3)) << 2);
    const int cA8 = (4 * t) ^ (((g & 3) ^ (((g >> 2) + 2) & 3)) << 2);
    int cB[4];
#pragma unroll
    for (int nt = 0; nt < 4; nt++)
        cB[nt] = (4 * t) ^ (((g & 3) ^ (((g >> 2) + 2 * nt) & 3)) << 2);

    float acc[4][4][4];
#pragma unroll
    for (int i = 0; i < 4; i++)
#pragma unroll
        for (int j = 0; j < 4; j++)
#pragma unroll
            for (int q = 0; q < 4; q++) acc[i][j][q] = 0.f;

    const int NC = K / 16;

#pragma unroll
    for (int c = 0; c < GS - 1; c++) {
        uint32_t so = (uint32_t)(c * GBUF * 4);
        const float* a = Ap + c * 16;
        const float* b = Bp + c * 16;
        cp16(dA0 + so, a);
        cp16(dA1 + so, a + 4);
        cp16(dB0 + so, b);
        cp16(dB1 + so, b + 4);
        CP_COMMIT();
    }

    for (int c = 0; c < NC; c++) {
        CP_WAIT(GS - 2);
        __syncthreads();

        int nc = c + GS - 1;
        if (nc < NC) {
            uint32_t so = (uint32_t)((nc % GS) * GBUF * 4);
            const float* a = Ap + nc * 16;
            const float* b = Bp + nc * 16;
            cp16(dA0 + so, a);
            cp16(dA1 + so, a + 4);
            cp16(dB0 + so, b);
            cp16(dB1 + so, b + 4);
        }
        CP_COMMIT();

        const int s = c % GS;
        const uint32_t* Ab = (const uint32_t*)(smem + s * GBUF);
        const uint32_t* Bb = (const uint32_t*)(smem + (GS + s) * GBUF);

        uint4 br[4];
#pragma unroll
        for (int nt = 0; nt < 4; nt++)
            br[nt] = *(const uint4*)&Bb[(wn + nt * 8 + g) * 16 + cB[nt]];

#pragma unroll
        for (int mt = 0; mt < 4; mt++) {
            const int r0 = wm + mt * 16 + g;
            uint4 ar0 = *(const uint4*)&Ab[r0 * 16 + cA0];
            uint4 ar1 = *(const uint4*)&Ab[(r0 + 8) * 16 + cA8];
#pragma unroll
            for (int nt = 0; nt < 4; nt++) {
                mma8v(acc[mt][nt], ar0.x, ar1.x, ar0.y, ar1.y, br[nt].x, br[nt].y);
                mma8v(acc[mt][nt], ar0.z, ar1.z, ar0.w, ar1.w, br[nt].z, br[nt].w);
            }
        }
    }

#pragma unroll
    for (int mt = 0; mt < 4; mt++) {
#pragma unroll
        for (int nt = 0; nt < 4; nt++) {
            int gcol = bn + wn + nt * 8 + 2 * t;
            float2 bv = *(const float2*)&bias[gcol];
            int r0 = bm + wm + mt * 16 + g;
#pragma unroll
            for (int hrow = 0; hrow < 2; hrow++) {
                int grow = r0 + hrow * 8;
                float c0 = acc[mt][nt][2 * hrow]     + bv.x;
                float c1 = acc[mt][nt][2 * hrow + 1] + bv.y;
                if (EPI == 1) {
                    size_t gidx = (size_t)grow * N + gcol;
                    float2 rv = *(const float2*)&res[gidx];
                    c0 += rv.x; c1 += rv.y;
                    *(float2*)&C[gidx] = make_float2(c0, c1);
                } else if (EPI == 0) {
                    size_t gidx = (size_t)grow * N + gcol;
                    *(float2*)&C[gidx] = make_float2(c0, c1);
                } else {
                    if (EPI == 2) {
                        c0 = c0 / (1.f + __expf(-1.702f * c0));
                        c1 = c1 / (1.f + __expf(-1.702f * c1));
                    }
                    int p  = gcol & 15;
                    int pp = ((p & 3) << 2) | (p >> 2);
                    size_t b16 = (size_t)grow * N + (gcol & ~15);
                    uint32_t u0, u1;
                    CVT_TF32(u0, c0); CVT_TF32(u1, c1);
                    ((uint32_t*)C)[b16 + pp]     = u0;
                    ((uint32_t*)C)[b16 + pp + 4] = u1;
                }
            }
        }
    }
}

// ---------------- Flash attention over permuted-tf32 qkv ----------------
// K staged via cp.async into Ks[64][80] (swizzled 16B units), fragment reads LDS.128.
// V packed to bf16x2 pairs Vp[32][72] (dh index = stored/permuted position).
// O comes out in permuted dh order -> linear stores already match next GEMM's layout.
#define KS_STR 80
#define VP_STR 72
#define ATT_SMEM ((64 * KS_STR + 32 * VP_STR) * 4)   // 29696 B

__global__ __launch_bounds__(128) void attn_mma(const float* __restrict__ qkv,
                                                float* __restrict__ o)
{
    extern __shared__ float asmem[];
    float*    Ks = asmem;                            // [64][KS_STR]
    uint32_t* Vp = (uint32_t*)(asmem + 64 * KS_STR); // [32][VP_STR]
    const uint32_t ksb_addr = smem_u32(asmem);

    const int tid  = threadIdx.x;
    const int lane = tid & 31;
    const int w    = tid >> 5;
    const int g = lane >> 2, t = lane & 3;
    const int qb = blockIdx.x * 64 + w * 16;
    const int h = blockIdx.y, n = blockIdx.z;

    const float qscale = 0.125f * 1.44269504088896f;

    // Q fragments from permuted gmem: block blk, half hf -> words blk*16+4t+2hf, +1
    uint32_t aq[8][4];
    {
        const uint32_t* qu = (const uint32_t*)qkv;
        size_t r0 = ((size_t)(qb + g) * NB + n) * E3 + h * DH;
        size_t r1 = ((size_t)(qb + g + 8) * NB + n) * E3 + h * DH;
#pragma unroll
        for (int blk = 0; blk < 4; blk++) {
#pragma unroll
            for (int hf = 0; hf < 2; hf++) {
                int off = blk * 16 + 4 * t + 2 * hf;
                uint2 q0 = *(const uint2*)&qu[r0 + off];
                uint2 q1 = *(const uint2*)&qu[r1 + off];
                int ch = 2 * blk + hf;
                CVT_TF32(aq[ch][0], __uint_as_float(q0.x) * qscale);
                CVT_TF32(aq[ch][1], __uint_as_float(q1.x) * qscale);
                CVT_TF32(aq[ch][2], __uint_as_float(q0.y) * qscale);
                CVT_TF32(aq[ch][3], __uint_as_float(q1.y) * qscale);
            }
        }
    }

    float oc[8][4];
#pragma unroll
    for (int i = 0; i < 8; i++)
#pragma unroll
        for (int j = 0; j < 4; j++) oc[i][j] = 0.f;
    float m0 = -1e30f, m1 = -1e30f, l0 = 0.f, l1 = 0.f;

    // K staging: thread -> (row srow, half hh). cp.async 8x16B.
    const int srow = tid >> 1;
    const int hh   = tid & 1;
    const int swu  = ((srow & 3) ^ ((srow >> 2) & 3));        // unit swizzle
    uint32_t kdst[8];
#pragma unroll
    for (int j = 0; j < 2; j++)
#pragma unroll
        for (int u = 0; u < 4; u++)
            kdst[j * 4 + u] = ksb_addr +
                (uint32_t)(KS_STR * srow + (2 * hh + j) * 16 + ((4 * u) ^ (swu << 2))) * 4;

    // V staging: thread -> (pair vr, quarter vq)
    const int vr = tid >> 2;
    const int vq = (tid & 3) * 16;

    // fragment read offsets: row r = nt*8+g
    int fc[8];
#pragma unroll
    for (int nt = 0; nt < 8; nt++) {
        int r = nt * 8 + g;
        fc[nt] = KS_STR * r + ((4 * t) ^ ((((r & 3) ^ ((r >> 2) & 3))) << 2));
    }

    for (int kb = 0; kb < L_SEQ / 64; kb++) {
        // ---- V row pair to regs (LDG overlaps barrier) ----
        size_t vb0 = ((size_t)(kb * 64 + 2 * vr)     * NB + n) * E3 + 2 * EMB + h * DH + vq;
        size_t vb1 = ((size_t)(kb * 64 + 2 * vr + 1) * NB + n) * E3 + 2 * EMB + h * DH + vq;
        float4 vr0[4], vr1[4];
#pragma unroll
        for (int i = 0; i < 4; i++) {
            vr0[i] = *(const float4*)&qkv[vb0 + 4 * i];
            vr1[i] = *(const float4*)&qkv[vb1 + 4 * i];
        }
        __syncthreads();   // prior tile fully consumed

        // ---- K via cp.async (gmem already tf32+permuted) ----
        {
            size_t kbase = ((size_t)(kb * 64 + srow) * NB + n) * E3 + EMB + h * DH + hh * 32;
#pragma unroll
            for (int j = 0; j < 2; j++)
#pragma unroll
                for (int u = 0; u < 4; u++)
                    cp16(kdst[j * 4 + u], &qkv[kbase + j * 16 + 4 * u]);
            CP_COMMIT();
        }

        // ---- V pack bf16x2 + STS ----
        {
            const float* f0 = (const float*)vr0;
            const float* f1 = (const float*)vr1;
            uint32_t* vp = &Vp[vr * VP_STR + vq];
#pragma unroll
            for (int i = 0; i < 4; i++) {
                uint4 cv;
                PACK_BF16X2(cv.x, f0[4*i],   f1[4*i]);
                PACK_BF16X2(cv.y, f0[4*i+1], f1[4*i+1]);
                PACK_BF16X2(cv.z, f0[4*i+2], f1[4*i+2]);
                PACK_BF16X2(cv.w, f0[4*i+3], f1[4*i+3]);
                *(uint4*)&vp[4 * i] = cv;
            }
        }
        CP_WAIT(0);
        __syncthreads();

        // ---- S = Q K^T (tf32, LDS.128 fragments) ----
        float sc[8][4];
#pragma unroll
        for (int i = 0; i < 8; i++)
#pragma unroll
            for (int j = 0; j < 4; j++) sc[i][j] = 0.f;

        const uint32_t* ksb = (const uint32_t*)Ks;
#pragma unroll
        for (int nt = 0; nt < 8; nt++) {
#pragma unroll
            for (int blk = 0; blk < 4; blk++) {
                uint4 kbv = *(const uint4*)&ksb[fc[nt] + 16 * blk];
                mma8v(sc[nt], aq[2*blk][0],   aq[2*blk][1],   aq[2*blk][2],   aq[2*blk][3],   kbv.x, kbv.y);
                mma8v(sc[nt], aq[2*blk+1][0], aq[2*blk+1][1], aq[2*blk+1][2], aq[2*blk+1][3], kbv.z, kbv.w);
            }
        }

        // ---- online softmax ----
        float tm0 = -1e30f, tm1 = -1e30f;
#pragma unroll
        for (int nt = 0; nt < 8; nt++) {
            tm0 = fmaxf(tm0, fmaxf(sc[nt][0], sc[nt][1]));
            tm1 = fmaxf(tm1, fmaxf(sc[nt][2], sc[nt][3]));
        }
        tm0 = fmaxf(tm0, __shfl_xor_sync(0xffffffffu, tm0, 1));
        tm0 = fmaxf(tm0, __shfl_xor_sync(0xffffffffu, tm0, 2));
        tm1 = fmaxf(tm1, __shfl_xor_sync(0xffffffffu, tm1, 1));
        tm1 = fmaxf(tm1, __shfl_xor_sync(0xffffffffu, tm1, 2));

        float nm0 = fmaxf(m0, tm0), nm1 = fmaxf(m1, tm1);
        float al0 = ex2f(m0 - nm0), al1 = ex2f(m1 - nm1);
        m0 = nm0; m1 = nm1;

        float s0 = 0.f, s1 = 0.f;
#pragma unroll
        for (int nt = 0; nt < 8; nt++) {
            sc[nt][0] = ex2f(sc[nt][0] - m0);
            sc[nt][1] = ex2f(sc[nt][1] - m0);
            sc[nt][2] = ex2f(sc[nt][2] - m1);
            sc[nt][3] = ex2f(sc[nt][3] - m1);
            s0 += sc[nt][0] + sc[nt][1];
            s1 += sc[nt][2] + sc[nt][3];
        }
        s0 += __shfl_xor_sync(0xffffffffu, s0, 1);
        s0 += __shfl_xor_sync(0xffffffffu, s0, 2);
        s1 += __shfl_xor_sync(0xffffffffu, s1, 1);
        s1 += __shfl_xor_sync(0xffffffffu, s1, 2);
        l0 = l0 * al0 + s0;
        l1 = l1 * al1 + s1;
#pragma unroll
        for (int nt = 0; nt < 8; nt++) {
            oc[nt][0] *= al0; oc[nt][1] *= al0;
            oc[nt][2] *= al1; oc[nt][3] *= al1;
        }

        // ---- O += P V (bf16, P direct from C fragments) ----
#pragma unroll
        for (int kk = 0; kk < 4; kk++) {
            uint32_t a0, a1, a2, a3;
            PACK_BF16X2(a0, sc[2*kk][0],   sc[2*kk][1]);
            PACK_BF16X2(a1, sc[2*kk][2],   sc[2*kk][3]);
            PACK_BF16X2(a2, sc[2*kk+1][0], sc[2*kk+1][1]);
            PACK_BF16X2(a3, sc[2*kk+1][2], sc[2*kk+1][3]);
#pragma unroll
            for (int nt = 0; nt < 8; nt++) {
                uint32_t b0 = Vp[(8 * kk + t)     * VP_STR + nt * 8 + g];
                uint32_t b1 = Vp[(8 * kk + t + 4) * VP_STR + nt * 8 + g];
                mma16bf(oc[nt], a0, a1, a2, a3, b0, b1);
            }
        }
    }

    // ---- epilogue: O already in permuted dh order -> linear tf32 stores ----
    float i0 = 1.f / l0, i1 = 1.f / l1;
    size_t o0 = ((size_t)(qb + g) * NB + n) * EMB + h * DH;
    size_t o1 = ((size_t)(qb + g + 8) * NB + n) * EMB + h * DH;
#pragma unroll
    for (int nt = 0; nt < 8; nt++) {
        int d = nt * 8 + 2 * t;
        uint2 u0, u1;
        CVT_TF32(u0.x, oc[nt][0] * i0); CVT_TF32(u0.y, oc[nt][1] * i0);
        CVT_TF32(u1.x, oc[nt][2] * i1); CVT_TF32(u1.y, oc[nt][3] * i1);
        *(uint2*)&((uint32_t*)o)[o0 + d] = u0;
        *(uint2*)&((uint32_t*)o)[o1 + d] = u1;
    }
}

// ---------------- launch ----------------
extern "C" void kernel_launch(void* const* d_in, const int* in_sizes, int n_in,
                              void* d_out, int out_size)
{
    const float* x      = (const float*)d_in[0];
    const float* ln1_w  = (const float*)d_in[1];
    const float* ln1_b  = (const float*)d_in[2];
    const float* w_qkv  = (const float*)d_in[3];
    const float* b_qkv  = (const float*)d_in[4];
    const float* w_out  = (const float*)d_in[5];
    const float* b_out  = (const float*)d_in[6];
    const float* ln2_w  = (const float*)d_in[7];
    const float* ln2_b  = (const float*)d_in[8];
    const float* w_fc   = (const float*)d_in[9];
    const float* b_fc   = (const float*)d_in[10];
    const float* w_proj = (const float*)d_in[11];
    const float* b_proj = (const float*)d_in[12];
    float* out = (float*)d_out;

    float *h, *qkv, *attn, *x1, *f, *wqkv, *wout, *wfc, *wproj;
    cudaGetSymbolAddress((void**)&h,     g_h);
    cudaGetSymbolAddress((void**)&qkv,   g_qkv);
    cudaGetSymbolAddress((void**)&attn,  g_attn);
    cudaGetSymbolAddress((void**)&x1,    g_x1);
    cudaGetSymbolAddress((void**)&f,     g_f);
    cudaGetSymbolAddress((void**)&wqkv,  g_wqkv);
    cudaGetSymbolAddress((void**)&wout,  g_wout);
    cudaGetSymbolAddress((void**)&wfc,   g_wfc);
    cudaGetSymbolAddress((void**)&wproj, g_wproj);

    cudaFuncSetAttribute(gemm_cp<1>, cudaFuncAttributeMaxDynamicSharedMemorySize, GT_SMEM);
    cudaFuncSetAttribute(gemm_cp<2>, cudaFuncAttributeMaxDynamicSharedMemorySize, GT_SMEM);
    cudaFuncSetAttribute(gemm_cp<3>, cudaFuncAttributeMaxDynamicSharedMemorySize, GT_SMEM);
    cudaFuncSetAttribute(attn_mma,   cudaFuncAttributeMaxDynamicSharedMemorySize, ATT_SMEM);

    int ptotal = S0 + S1 + S2 + S3;
    permute_all<<<(ptotal + 255) / 256, 256>>>(w_qkv, wqkv, w_out, wout,
                                               w_fc, wfc, w_proj, wproj);

    ln_kernel<<<ROWS, 256>>>(x, ln1_w, ln1_b, h);
    gemm_cp<3><<<dim3(E3 / 128, ROWS / 128), 256, GT_SMEM>>>(h, wqkv, b_qkv, nullptr, qkv,
                                                             ROWS, E3, EMB);
    attn_mma<<<dim3(L_SEQ / 64, NHEAD, NB), 128, ATT_SMEM>>>(qkv, attn);
    gemm_cp<1><<<dim3(EMB / 128, ROWS / 128), 256, GT_SMEM>>>(attn, wout, b_out, x, x1,
                                                              ROWS, EMB, EMB);
    ln_kernel<<<ROWS, 256>>>(x1, ln2_w, ln2_b, h);
    gemm_cp<2><<<dim3(E4 / 128, ROWS / 128), 256, GT_SMEM>>>(h, wfc, b_fc, nullptr, f,
                                                             ROWS, E4, EMB);
    gemm_cp<1><<<dim3(EMB / 128, ROWS / 128), 256, GT_SMEM>>>(f, wproj, b_proj, x1, out,
                                                              ROWS, EMB, E4);
}

// round 14
// speedup vs baseline: 1.3544x; 1.0131x over previous
#include <cuda_runtime.h>
#include <math.h>
#include <stdint.h>

#define L_SEQ  2048
#define NB     4
#define EMB    768
#define NHEAD  12
#define DH     64
#define ROWS   (L_SEQ * NB)      // 8192
#define E3     (3 * EMB)         // 2304
#define E4     (4 * EMB)         // 3072

// ---------------- scratch ----------------
__device__ float g_h   [ (size_t)ROWS * EMB ];
__device__ float g_qkv [ (size_t)ROWS * E3  ];   // tf32 + k-permuted
__device__ float g_attn[ (size_t)ROWS * EMB ];   // tf32 + k-permuted
__device__ float g_x1  [ (size_t)ROWS * EMB ];
__device__ float g_f   [ (size_t)ROWS * E4  ];
__device__ float g_wqkv [ (size_t)E3  * EMB ];
__device__ float g_wout [ (size_t)EMB * EMB ];
__device__ float g_wfc  [ (size_t)E4  * EMB ];
__device__ float g_wproj[ (size_t)EMB * E4  ];

#define CVT_TF32(d, s) asm volatile("cvt.rna.tf32.f32 %0, %1;" : "=r"(d) : "f"(s))
#define PACK_BF16X2(d, lo, hi) \
    asm volatile("cvt.rn.bf16x2.f32 %0, %1, %2;" : "=r"(d) : "f"(hi), "f"(lo))

__device__ __forceinline__ uint32_t smem_u32(const void* p) {
    uint32_t a;
    asm("{ .reg .u64 t; cvta.to.shared.u64 t, %1; cvt.u32.u64 %0, t; }" : "=r"(a) : "l"(p));
    return a;
}
__device__ __forceinline__ void cp16(uint32_t dst, const void* src) {
    asm volatile("cp.async.cg.shared.global [%0], [%1], 16;" :: "r"(dst), "l"(src));
}
#define CP_COMMIT() asm volatile("cp.async.commit_group;" ::: "memory")
#define CP_WAIT(n)  asm volatile("cp.async.wait_group %0;" :: "n"(n) : "memory")

__device__ __forceinline__ float ex2f(float x) {
    float y; asm("ex2.approx.f32 %0, %1;" : "=f"(y) : "f"(x)); return y;
}
__device__ __forceinline__ void mma8v(float* c,
                                      uint32_t a0, uint32_t a1, uint32_t a2, uint32_t a3,
                                      uint32_t b0, uint32_t b1) {
    asm volatile(
        "mma.sync.aligned.m16n8k8.row.col.f32.tf32.tf32.f32 "
        "{%0,%1,%2,%3}, {%4,%5,%6,%7}, {%8,%9}, {%0,%1,%2,%3};"
        : "+f"(c[0]), "+f"(c[1]), "+f"(c[2]), "+f"(c[3])
        : "r"(a0), "r"(a1), "r"(a2), "r"(a3), "r"(b0), "r"(b1));
}
__device__ __forceinline__ void mma16bf(float* c,
                                        uint32_t a0, uint32_t a1, uint32_t a2, uint32_t a3,
                                        uint32_t b0, uint32_t b1) {
    asm volatile(
        "mma.sync.aligned.m16n8k16.row.col.f32.bf16.bf16.f32 "
        "{%0,%1,%2,%3}, {%4,%5,%6,%7}, {%8,%9}, {%0,%1,%2,%3};"
        : "+f"(c[0]), "+f"(c[1]), "+f"(c[2]), "+f"(c[3])
        : "r"(a0), "r"(a1), "r"(a2), "r"(a3), "r"(b0), "r"(b1));
}

// ---------------- merged weight permute + tf32 round ----------------
#define S0 (E3 * EMB)
#define S1 (EMB * EMB)
#define S2 (E4 * EMB)
#define S3 (EMB * E4)
__global__ __launch_bounds__(256) void permute_all(
    const float* __restrict__ w0, float* __restrict__ o0,
    const float* __restrict__ w1, float* __restrict__ o1,
    const float* __restrict__ w2, float* __restrict__ o2,
    const float* __restrict__ w3, float* __restrict__ o3)
{
    int i = blockIdx.x * 256 + threadIdx.x;
    const float* in; float* out; int idx = i;
    if (idx < S0)              { in = w0; out = o0; }
    else if ((idx -= S0) < S1) { in = w1; out = o1; }
    else if ((idx -= S1) < S2) { in = w2; out = o2; }
    else {
        idx -= S2;
        if (idx >= S3) return;
        in = w3; out = o3;
    }
    int j  = idx & 15;
    int pj = ((j & 3) << 2) | (j >> 2);
    uint32_t v; CVT_TF32(v, in[idx]);
    ((uint32_t*)out)[(idx & ~15) | pj] = v;
}

// ---------------- LayerNorm: warp-per-row, shfl-only reduce, permuted tf32 out ----------------
__global__ __launch_bounds__(256) void ln_kernel(const float* __restrict__ x,
                                                 const float* __restrict__ w,
                                                 const float* __restrict__ b,
                                                 float* __restrict__ out)
{
    const int warp = threadIdx.x >> 5;
    const int lane = threadIdx.x & 31;
    const int row  = blockIdx.x * 8 + warp;

    const float* xr = x + (size_t)row * EMB;
    uint32_t* orow = (uint32_t*)(out + (size_t)row * EMB);

    float v[24];
    float sum = 0.f, sq = 0.f;
#pragma unroll
    for (int i = 0; i < 6; i++) {
        float4 f = *(const float4*)&xr[128 * i + lane * 4];
        v[4*i] = f.x; v[4*i+1] = f.y; v[4*i+2] = f.z; v[4*i+3] = f.w;
        sum += f.x + f.y + f.z + f.w;
        sq  += f.x*f.x + f.y*f.y + f.z*f.z + f.w*f.w;
    }
#pragma unroll
    for (int o = 16; o > 0; o >>= 1) {
        sum += __shfl_xor_sync(0xffffffffu, sum, o);
        sq  += __shfl_xor_sync(0xffffffffu, sq,  o);
    }
    float mu   = sum * (1.0f / EMB);
    float var  = sq * (1.0f / EMB) - mu * mu;
    float rstd = rsqrtf(var + 1e-5f);

    const int s = lane & 3;                 // perm sub-position
#pragma unroll
    for (int i = 0; i < 6; i++) {
        int c    = 128 * i + lane * 4;
        int base = c & ~15;
        float4 wv = *(const float4*)&w[c];
        float4 bv = *(const float4*)&b[c];
        float y0 = (v[4*i]   - mu) * rstd * wv.x + bv.x;
        float y1 = (v[4*i+1] - mu) * rstd * wv.y + bv.y;
        float y2 = (v[4*i+2] - mu) * rstd * wv.z + bv.z;
        float y3 = (v[4*i+3] - mu) * rstd * wv.w + bv.w;
        uint32_t u0, u1, u2, u3;
        CVT_TF32(u0, y0); CVT_TF32(u1, y1); CVT_TF32(u2, y2); CVT_TF32(u3, y3);
        orow[base + s]      = u0;   // perm(q*1): elems q map to 4q+s
        orow[base + 4 + s]  = u1;
        orow[base + 8 + s]  = u2;
        orow[base + 12 + s] = u3;
    }
}

// ---------------- cp.async tf32 GEMM (k16 stages, GS=4) ----------------
// EPI 0: plain  1: +res  2: QuickGELU+permuted  3: plain+permuted
#define GS 4
#define GBUF (128 * 16)
#define GT_SMEM (GS * 2 * GBUF * 4)         // 65536

template <int EPI>
__global__ __launch_bounds__(256, 2) void gemm_cp(
    const float* __restrict__ A, const float* __restrict__ B,
    const float* __restrict__ bias, const float* __restrict__ res,
    float* __restrict__ C, int M, int N, int K)
{
    extern __shared__ float smem[];
    const uint32_t sb = smem_u32(smem);

    const int tid  = threadIdx.x;
    const int wid  = tid >> 5;
    const int lane = tid & 31;
    const int g = lane >> 2, t = lane & 3;

    const int bm = blockIdx.y * 128;
    const int bn = blockIdx.x * 128;
    const int wm = (wid >> 2) * 64;
    const int wn = (wid & 3) * 32;

    const int lr = tid >> 1;
    const int hc = (tid & 1) * 2;
    const int sw = ((lr & 3) ^ ((lr >> 2) & 3)) << 2;
    const float* Ap = A + (size_t)(bm + lr) * K + hc * 4;
    const float* Bp = B + (size_t)(bn + lr) * K + hc * 4;
    const uint32_t dA0 = sb + (lr * 16 + ((4 * hc)     ^ sw)) * 4;
    const uint32_t dA1 = sb + (lr * 16 + ((4 * hc + 4) ^ sw)) * 4;
    const uint32_t dB0 = dA0 + GS * GBUF * 4;
    const uint32_t dB1 = dA1 + GS * GBUF * 4;

    const int cA0 = (4 * t) ^ (((g & 3) ^ ((g >> 2) & 3)) << 2);
    const int cA8 = (4 * t) ^ (((g & 3) ^ (((g >> 2) + 2) & 3)) << 2);
    int cB[4];
#pragma unroll
    for (int nt = 0; nt < 4; nt++)
        cB[nt] = (4 * t) ^ (((g & 3) ^ (((g >> 2) + 2 * nt) & 3)) << 2);

    float acc[4][4][4];
#pragma unroll
    for (int i = 0; i < 4; i++)
#pragma unroll
        for (int j = 0; j < 4; j++)
#pragma unroll
            for (int q = 0; q < 4; q++) acc[i][j][q] = 0.f;

    const int NC = K / 16;

#pragma unroll
    for (int c = 0; c < GS - 1; c++) {
        uint32_t so = (uint32_t)(c * GBUF * 4);
        const float* a = Ap + c * 16;
        const float* b = Bp + c * 16;
        cp16(dA0 + so, a);
        cp16(dA1 + so, a + 4);
        cp16(dB0 + so, b);
        cp16(dB1 + so, b + 4);
        CP_COMMIT();
    }

    for (int c = 0; c < NC; c++) {
        CP_WAIT(GS - 2);
        __syncthreads();

        int nc = c + GS - 1;
        if (nc < NC) {
            uint32_t so = (uint32_t)((nc % GS) * GBUF * 4);
            const float* a = Ap + nc * 16;
            const float* b = Bp + nc * 16;
            cp16(dA0 + so, a);
            cp16(dA1 + so, a + 4);
            cp16(dB0 + so, b);
            cp16(dB1 + so, b + 4);
        }
        CP_COMMIT();

        const int s = c % GS;
        const uint32_t* Ab = (const uint32_t*)(smem + s * GBUF);
        const uint32_t* Bb = (const uint32_t*)(smem + (GS + s) * GBUF);

        uint4 br[4];
#pragma unroll
        for (int nt = 0; nt < 4; nt++)
            br[nt] = *(const uint4*)&Bb[(wn + nt * 8 + g) * 16 + cB[nt]];

#pragma unroll
        for (int mt = 0; mt < 4; mt++) {
            const int r0 = wm + mt * 16 + g;
            uint4 ar0 = *(const uint4*)&Ab[r0 * 16 + cA0];
            uint4 ar1 = *(const uint4*)&Ab[(r0 + 8) * 16 + cA8];
#pragma unroll
            for (int nt = 0; nt < 4; nt++) {
                mma8v(acc[mt][nt], ar0.x, ar1.x, ar0.y, ar1.y, br[nt].x, br[nt].y);
                mma8v(acc[mt][nt], ar0.z, ar1.z, ar0.w, ar1.w, br[nt].z, br[nt].w);
            }
        }
    }

#pragma unroll
    for (int mt = 0; mt < 4; mt++) {
#pragma unroll
        for (int nt = 0; nt < 4; nt++) {
            int gcol = bn + wn + nt * 8 + 2 * t;
            float2 bv = *(const float2*)&bias[gcol];
            int r0 = bm + wm + mt * 16 + g;
#pragma unroll
            for (int hrow = 0; hrow < 2; hrow++) {
                int grow = r0 + hrow * 8;
                float c0 = acc[mt][nt][2 * hrow]     + bv.x;
                float c1 = acc[mt][nt][2 * hrow + 1] + bv.y;
                if (EPI == 1) {
                    size_t gidx = (size_t)grow * N + gcol;
                    float2 rv = *(const float2*)&res[gidx];
                    c0 += rv.x; c1 += rv.y;
                    *(float2*)&C[gidx] = make_float2(c0, c1);
                } else if (EPI == 0) {
                    size_t gidx = (size_t)grow * N + gcol;
                    *(float2*)&C[gidx] = make_float2(c0, c1);
                } else {
                    if (EPI == 2) {
                        c0 = c0 / (1.f + __expf(-1.702f * c0));
                        c1 = c1 / (1.f + __expf(-1.702f * c1));
                    }
                    int p  = gcol & 15;
                    int pp = ((p & 3) << 2) | (p >> 2);
                    size_t b16 = (size_t)grow * N + (gcol & ~15);
                    uint32_t u0, u1;
                    CVT_TF32(u0, c0); CVT_TF32(u1, c1);
                    ((uint32_t*)C)[b16 + pp]     = u0;
                    ((uint32_t*)C)[b16 + pp + 4] = u1;
                }
            }
        }
    }
}

// ---------------- Flash attention over permuted-tf32 qkv ----------------
#define KS_STR 80
#define VP_STR 72
#define ATT_SMEM ((64 * KS_STR + 32 * VP_STR) * 4)   // 29696 B

__global__ __launch_bounds__(128, 4) void attn_mma(const float* __restrict__ qkv,
                                                   float* __restrict__ o)
{
    extern __shared__ float asmem[];
    float*    Ks = asmem;                            // [64][KS_STR]
    uint32_t* Vp = (uint32_t*)(asmem + 64 * KS_STR); // [32][VP_STR]
    const uint32_t ksb_addr = smem_u32(asmem);

    const int tid  = threadIdx.x;
    const int lane = tid & 31;
    const int w    = tid >> 5;
    const int g = lane >> 2, t = lane & 3;
    const int qb = blockIdx.x * 64 + w * 16;
    const int h = blockIdx.y, n = blockIdx.z;

    const float qscale = 0.125f * 1.44269504088896f;

    uint32_t aq[8][4];
    {
        const uint32_t* qu = (const uint32_t*)qkv;
        size_t r0 = ((size_t)(qb + g) * NB + n) * E3 + h * DH;
        size_t r1 = ((size_t)(qb + g + 8) * NB + n) * E3 + h * DH;
#pragma unroll
        for (int blk = 0; blk < 4; blk++) {
#pragma unroll
            for (int hf = 0; hf < 2; hf++) {
                int off = blk * 16 + 4 * t + 2 * hf;
                uint2 q0 = *(const uint2*)&qu[r0 + off];
                uint2 q1 = *(const uint2*)&qu[r1 + off];
                int ch = 2 * blk + hf;
                CVT_TF32(aq[ch][0], __uint_as_float(q0.x) * qscale);
                CVT_TF32(aq[ch][1], __uint_as_float(q1.x) * qscale);
                CVT_TF32(aq[ch][2], __uint_as_float(q0.y) * qscale);
                CVT_TF32(aq[ch][3], __uint_as_float(q1.y) * qscale);
            }
        }
    }

    float oc[8][4];
#pragma unroll
    for (int i = 0; i < 8; i++)
#pragma unroll
        for (int j = 0; j < 4; j++) oc[i][j] = 0.f;
    float m0 = -1e30f, m1 = -1e30f, l0 = 0.f, l1 = 0.f;

    const int srow = tid >> 1;
    const int hh   = tid & 1;
    const int swu  = ((srow & 3) ^ ((srow >> 2) & 3));
    uint32_t kdst[8];
#pragma unroll
    for (int j = 0; j < 2; j++)
#pragma unroll
        for (int u = 0; u < 4; u++)
            kdst[j * 4 + u] = ksb_addr +
                (uint32_t)(KS_STR * srow + (2 * hh + j) * 16 + ((4 * u) ^ (swu << 2))) * 4;

    const int vr = tid >> 2;
    const int vq = (tid & 3) * 16;

    int fc[8];
#pragma unroll
    for (int nt = 0; nt < 8; nt++) {
        int r = nt * 8 + g;
        fc[nt] = KS_STR * r + ((4 * t) ^ ((((r & 3) ^ ((r >> 2) & 3))) << 2));
    }

    for (int kb = 0; kb < L_SEQ / 64; kb++) {
        size_t vb0 = ((size_t)(kb * 64 + 2 * vr)     * NB + n) * E3 + 2 * EMB + h * DH + vq;
        size_t vb1 = ((size_t)(kb * 64 + 2 * vr + 1) * NB + n) * E3 + 2 * EMB + h * DH + vq;
        float4 vr0[4], vr1[4];
#pragma unroll
        for (int i = 0; i < 4; i++) {
            vr0[i] = *(const float4*)&qkv[vb0 + 4 * i];
            vr1[i] = *(const float4*)&qkv[vb1 + 4 * i];
        }
        __syncthreads();

        {
            size_t kbase = ((size_t)(kb * 64 + srow) * NB + n) * E3 + EMB + h * DH + hh * 32;
#pragma unroll
            for (int j = 0; j < 2; j++)
#pragma unroll
                for (int u = 0; u < 4; u++)
                    cp16(kdst[j * 4 + u], &qkv[kbase + j * 16 + 4 * u]);
            CP_COMMIT();
        }

        {
            const float* f0 = (const float*)vr0;
            const float* f1 = (const float*)vr1;
            uint32_t* vp = &Vp[vr * VP_STR + vq];
#pragma unroll
            for (int i = 0; i < 4; i++) {
                uint4 cv;
                PACK_BF16X2(cv.x, f0[4*i],   f1[4*i]);
                PACK_BF16X2(cv.y, f0[4*i+1], f1[4*i+1]);
                PACK_BF16X2(cv.z, f0[4*i+2], f1[4*i+2]);
                PACK_BF16X2(cv.w, f0[4*i+3], f1[4*i+3]);
                *(uint4*)&vp[4 * i] = cv;
            }
        }
        CP_WAIT(0);
        __syncthreads();

        float sc[8][4];
#pragma unroll
        for (int i = 0; i < 8; i++)
#pragma unroll
            for (int j = 0; j < 4; j++) sc[i][j] = 0.f;

        const uint32_t* ksb = (const uint32_t*)Ks;
#pragma unroll
        for (int nt = 0; nt < 8; nt++) {
#pragma unroll
            for (int blk = 0; blk < 4; blk++) {
                uint4 kbv = *(const uint4*)&ksb[fc[nt] + 16 * blk];
                mma8v(sc[nt], aq[2*blk][0],   aq[2*blk][1],   aq[2*blk][2],   aq[2*blk][3],   kbv.x, kbv.y);
                mma8v(sc[nt], aq[2*blk+1][0], aq[2*blk+1][1], aq[2*blk+1][2], aq[2*blk+1][3], kbv.z, kbv.w);
            }
        }

        float tm0 = -1e30f, tm1 = -1e30f;
#pragma unroll
        for (int nt = 0; nt < 8; nt++) {
            tm0 = fmaxf(tm0, fmaxf(sc[nt][0], sc[nt][1]));
            tm1 = fmaxf(tm1, fmaxf(sc[nt][2], sc[nt][3]));
        }
        tm0 = fmaxf(tm0, __shfl_xor_sync(0xffffffffu, tm0, 1));
        tm0 = fmaxf(tm0, __shfl_xor_sync(0xffffffffu, tm0, 2));
        tm1 = fmaxf(tm1, __shfl_xor_sync(0xffffffffu, tm1, 1));
        tm1 = fmaxf(tm1, __shfl_xor_sync(0xffffffffu, tm1, 2));

        float nm0 = fmaxf(m0, tm0), nm1 = fmaxf(m1, tm1);
        float al0 = ex2f(m0 - nm0), al1 = ex2f(m1 - nm1);
        m0 = nm0; m1 = nm1;

        float s0 = 0.f, s1 = 0.f;
#pragma unroll
        for (int nt = 0; nt < 8; nt++) {
            sc[nt][0] = ex2f(sc[nt][0] - m0);
            sc[nt][1] = ex2f(sc[nt][1] - m0);
            sc[nt][2] = ex2f(sc[nt][2] - m1);
            sc[nt][3] = ex2f(sc[nt][3] - m1);
            s0 += sc[nt][0] + sc[nt][1];
            s1 += sc[nt][2] + sc[nt][3];
        }
        s0 += __shfl_xor_sync(0xffffffffu, s0, 1);
        s0 += __shfl_xor_sync(0xffffffffu, s0, 2);
        s1 += __shfl_xor_sync(0xffffffffu, s1, 1);
        s1 += __shfl_xor_sync(0xffffffffu, s1, 2);
        l0 = l0 * al0 + s0;
        l1 = l1 * al1 + s1;
#pragma unroll
        for (int nt = 0; nt < 8; nt++) {
            oc[nt][0] *= al0; oc[nt][1] *= al0;
            oc[nt][2] *= al1; oc[nt][3] *= al1;
        }

#pragma unroll
        for (int kk = 0; kk < 4; kk++) {
            uint32_t a0, a1, a2, a3;
            PACK_BF16X2(a0, sc[2*kk][0],   sc[2*kk][1]);
            PACK_BF16X2(a1, sc[2*kk][2],   sc[2*kk][3]);
            PACK_BF16X2(a2, sc[2*kk+1][0], sc[2*kk+1][1]);
            PACK_BF16X2(a3, sc[2*kk+1][2], sc[2*kk+1][3]);
#pragma unroll
            for (int nt = 0; nt < 8; nt++) {
                uint32_t b0 = Vp[(8 * kk + t)     * VP_STR + nt * 8 + g];
                uint32_t b1 = Vp[(8 * kk + t + 4) * VP_STR + nt * 8 + g];
                mma16bf(oc[nt], a0, a1, a2, a3, b0, b1);
            }
        }
    }

    float i0 = 1.f / l0, i1 = 1.f / l1;
    size_t o0 = ((size_t)(qb + g) * NB + n) * EMB + h * DH;
    size_t o1 = ((size_t)(qb + g + 8) * NB + n) * EMB + h * DH;
#pragma unroll
    for (int nt = 0; nt < 8; nt++) {
        int d = nt * 8 + 2 * t;
        uint2 u0, u1;
        CVT_TF32(u0.x, oc[nt][0] * i0); CVT_TF32(u0.y, oc[nt][1] * i0);
        CVT_TF32(u1.x, oc[nt][2] * i1); CVT_TF32(u1.y, oc[nt][3] * i1);
        *(uint2*)&((uint32_t*)o)[o0 + d] = u0;
        *(uint2*)&((uint32_t*)o)[o1 + d] = u1;
    }
}

// ---------------- launch ----------------
extern "C" void kernel_launch(void* const* d_in, const int* in_sizes, int n_in,
                              void* d_out, int out_size)
{
    const float* x      = (const float*)d_in[0];
    const float* ln1_w  = (const float*)d_in[1];
    const float* ln1_b  = (const float*)d_in[2];
    const float* w_qkv  = (const float*)d_in[3];
    const float* b_qkv  = (const float*)d_in[4];
    const float* w_out  = (const float*)d_in[5];
    const float* b_out  = (const float*)d_in[6];
    const float* ln2_w  = (const float*)d_in[7];
    const float* ln2_b  = (const float*)d_in[8];
    const float* w_fc   = (const float*)d_in[9];
    const float* b_fc   = (const float*)d_in[10];
    const float* w_proj = (const float*)d_in[11];
    const float* b_proj = (const float*)d_in[12];
    float* out = (float*)d_out;

    float *h, *qkv, *attn, *x1, *f, *wqkv, *wout, *wfc, *wproj;
    cudaGetSymbolAddress((void**)&h,     g_h);
    cudaGetSymbolAddress((void**)&qkv,   g_qkv);
    cudaGetSymbolAddress((void**)&attn,  g_attn);
    cudaGetSymbolAddress((void**)&x1,    g_x1);
    cudaGetSymbolAddress((void**)&f,     g_f);
    cudaGetSymbolAddress((void**)&wqkv,  g_wqkv);
    cudaGetSymbolAddress((void**)&wout,  g_wout);
    cudaGetSymbolAddress((void**)&wfc,   g_wfc);
    cudaGetSymbolAddress((void**)&wproj, g_wproj);

    cudaFuncSetAttribute(gemm_cp<1>, cudaFuncAttributeMaxDynamicSharedMemorySize, GT_SMEM);
    cudaFuncSetAttribute(gemm_cp<2>, cudaFuncAttributeMaxDynamicSharedMemorySize, GT_SMEM);
    cudaFuncSetAttribute(gemm_cp<3>, cudaFuncAttributeMaxDynamicSharedMemorySize, GT_SMEM);
    cudaFuncSetAttribute(attn_mma,   cudaFuncAttributeMaxDynamicSharedMemorySize, ATT_SMEM);

    int ptotal = S0 + S1 + S2 + S3;
    permute_all<<<(ptotal + 255) / 256, 256>>>(w_qkv, wqkv, w_out, wout,
                                               w_fc, wfc, w_proj, wproj);

    ln_kernel<<<ROWS / 8, 256>>>(x, ln1_w, ln1_b, h);
    gemm_cp<3><<<dim3(E3 / 128, ROWS / 128), 256, GT_SMEM>>>(h, wqkv, b_qkv, nullptr, qkv,
                                                             ROWS, E3, EMB);
    attn_mma<<<dim3(L_SEQ / 64, NHEAD, NB), 128, ATT_SMEM>>>(qkv, attn);
    gemm_cp<1><<<dim3(EMB / 128, ROWS / 128), 256, GT_SMEM>>>(attn, wout, b_out, x, x1,
                                                              ROWS, EMB, EMB);
    ln_kernel<<<ROWS / 8, 256>>>(x1, ln2_w, ln2_b, h);
    gemm_cp<2><<<dim3(E4 / 128, ROWS / 128), 256, GT_SMEM>>>(h, wfc, b_fc, nullptr, f,
                                                             ROWS, E4, EMB);
    gemm_cp<1><<<dim3(EMB / 128, ROWS / 128), 256, GT_SMEM>>>(f, wproj, b_proj, x1, out,
                                                              ROWS, EMB, E4);
}

// round 15
// speedup vs baseline: 1.4398x; 1.0630x over previous
#include <cuda_runtime.h>
#include <math.h>
#include <stdint.h>

#define L_SEQ  2048
#define NB     4
#define EMB    768
#define NHEAD  12
#define DH     64
#define ROWS   (L_SEQ * NB)      // 8192
#define E3     (3 * EMB)         // 2304
#define E4     (4 * EMB)         // 3072

// ---------------- scratch ----------------
__device__ float g_h   [ (size_t)ROWS * EMB ];
__device__ float g_qkv [ (size_t)ROWS * E3  ];   // tf32 + k-permuted
__device__ float g_attn[ (size_t)ROWS * EMB ];   // tf32 + k-permuted
__device__ float g_x1  [ (size_t)ROWS * EMB ];
__device__ float g_f   [ (size_t)ROWS * E4  ];
__device__ float g_wqkv [ (size_t)E3  * EMB ];
__device__ float g_wout [ (size_t)EMB * EMB ];
__device__ float g_wfc  [ (size_t)E4  * EMB ];
__device__ float g_wproj[ (size_t)EMB * E4  ];

#define CVT_TF32(d, s) asm volatile("cvt.rna.tf32.f32 %0, %1;" : "=r"(d) : "f"(s))
#define PACK_BF16X2(d, lo, hi) \
    asm volatile("cvt.rn.bf16x2.f32 %0, %1, %2;" : "=r"(d) : "f"(hi), "f"(lo))

__device__ __forceinline__ uint32_t smem_u32(const void* p) {
    uint32_t a;
    asm("{ .reg .u64 t; cvta.to.shared.u64 t, %1; cvt.u32.u64 %0, t; }" : "=r"(a) : "l"(p));
    return a;
}
__device__ __forceinline__ void cp16(uint32_t dst, const void* src) {
    asm volatile("cp.async.cg.shared.global [%0], [%1], 16;" :: "r"(dst), "l"(src));
}
#define CP_COMMIT() asm volatile("cp.async.commit_group;" ::: "memory")
#define CP_WAIT(n)  asm volatile("cp.async.wait_group %0;" :: "n"(n) : "memory")

__device__ __forceinline__ float ex2f(float x) {
    float y; asm("ex2.approx.f32 %0, %1;" : "=f"(y) : "f"(x)); return y;
}
__device__ __forceinline__ void mma8v(float* c,
                                      uint32_t a0, uint32_t a1, uint32_t a2, uint32_t a3,
                                      uint32_t b0, uint32_t b1) {
    asm volatile(
        "mma.sync.aligned.m16n8k8.row.col.f32.tf32.tf32.f32 "
        "{%0,%1,%2,%3}, {%4,%5,%6,%7}, {%8,%9}, {%0,%1,%2,%3};"
        : "+f"(c[0]), "+f"(c[1]), "+f"(c[2]), "+f"(c[3])
        : "r"(a0), "r"(a1), "r"(a2), "r"(a3), "r"(b0), "r"(b1));
}
__device__ __forceinline__ void mma16bf(float* c,
                                        uint32_t a0, uint32_t a1, uint32_t a2, uint32_t a3,
                                        uint32_t b0, uint32_t b1) {
    asm volatile(
        "mma.sync.aligned.m16n8k16.row.col.f32.bf16.bf16.f32 "
        "{%0,%1,%2,%3}, {%4,%5,%6,%7}, {%8,%9}, {%0,%1,%2,%3};"
        : "+f"(c[0]), "+f"(c[1]), "+f"(c[2]), "+f"(c[3])
        : "r"(a0), "r"(a1), "r"(a2), "r"(a3), "r"(b0), "r"(b1));
}

// ---------------- merged weight permute + tf32 round ----------------
#define S0 (E3 * EMB)
#define S1 (EMB * EMB)
#define S2 (E4 * EMB)
#define S3 (EMB * E4)
__global__ __launch_bounds__(256) void permute_all(
    const float* __restrict__ w0, float* __restrict__ o0,
    const float* __restrict__ w1, float* __restrict__ o1,
    const float* __restrict__ w2, float* __restrict__ o2,
    const float* __restrict__ w3, float* __restrict__ o3)
{
    int i = blockIdx.x * 256 + threadIdx.x;
    const float* in; float* out; int idx = i;
    if (idx < S0)              { in = w0; out = o0; }
    else if ((idx -= S0) < S1) { in = w1; out = o1; }
    else if ((idx -= S1) < S2) { in = w2; out = o2; }
    else {
        idx -= S2;
        if (idx >= S3) return;
        in = w3; out = o3;
    }
    int j  = idx & 15;
    int pj = ((j & 3) << 2) | (j >> 2);
    uint32_t v; CVT_TF32(v, in[idx]);
    ((uint32_t*)out)[(idx & ~15) | pj] = v;
}

// ---------------- LayerNorm: warp-per-row, shfl-only reduce, permuted tf32 out ----------------
__global__ __launch_bounds__(256) void ln_kernel(const float* __restrict__ x,
                                                 const float* __restrict__ w,
                                                 const float* __restrict__ b,
                                                 float* __restrict__ out)
{
    const int warp = threadIdx.x >> 5;
    const int lane = threadIdx.x & 31;
    const int row  = blockIdx.x * 8 + warp;

    const float* xr = x + (size_t)row * EMB;
    uint32_t* orow = (uint32_t*)(out + (size_t)row * EMB);

    float v[24];
    float sum = 0.f, sq = 0.f;
#pragma unroll
    for (int i = 0; i < 6; i++) {
        float4 f = *(const float4*)&xr[128 * i + lane * 4];
        v[4*i] = f.x; v[4*i+1] = f.y; v[4*i+2] = f.z; v[4*i+3] = f.w;
        sum += f.x + f.y + f.z + f.w;
        sq  += f.x*f.x + f.y*f.y + f.z*f.z + f.w*f.w;
    }
#pragma unroll
    for (int o = 16; o > 0; o >>= 1) {
        sum += __shfl_xor_sync(0xffffffffu, sum, o);
        sq  += __shfl_xor_sync(0xffffffffu, sq,  o);
    }
    float mu   = sum * (1.0f / EMB);
    float var  = sq * (1.0f / EMB) - mu * mu;
    float rstd = rsqrtf(var + 1e-5f);

    const int s = lane & 3;
#pragma unroll
    for (int i = 0; i < 6; i++) {
        int c    = 128 * i + lane * 4;
        int base = c & ~15;
        float4 wv = *(const float4*)&w[c];
        float4 bv = *(const float4*)&b[c];
        float y0 = (v[4*i]   - mu) * rstd * wv.x + bv.x;
        float y1 = (v[4*i+1] - mu) * rstd * wv.y + bv.y;
        float y2 = (v[4*i+2] - mu) * rstd * wv.z + bv.z;
        float y3 = (v[4*i+3] - mu) * rstd * wv.w + bv.w;
        uint32_t u0, u1, u2, u3;
        CVT_TF32(u0, y0); CVT_TF32(u1, y1); CVT_TF32(u2, y2); CVT_TF32(u3, y3);
        orow[base + s]      = u0;
        orow[base + 4 + s]  = u1;
        orow[base + 8 + s]  = u2;
        orow[base + 12 + s] = u3;
    }
}

// ---------------- cp.async tf32 GEMM (k16 stages, GS=4) ----------------
#define GS 4
#define GBUF (128 * 16)
#define GT_SMEM (GS * 2 * GBUF * 4)         // 65536

template <int EPI>
__global__ __launch_bounds__(256, 2) void gemm_cp(
    const float* __restrict__ A, const float* __restrict__ B,
    const float* __restrict__ bias, const float* __restrict__ res,
    float* __restrict__ C, int M, int N, int K)
{
    extern __shared__ float smem[];
    const uint32_t sb = smem_u32(smem);

    const int tid  = threadIdx.x;
    const int wid  = tid >> 5;
    const int lane = tid & 31;
    const int g = lane >> 2, t = lane & 3;

    const int bm = blockIdx.y * 128;
    const int bn = blockIdx.x * 128;
    const int wm = (wid >> 2) * 64;
    const int wn = (wid & 3) * 32;

    const int lr = tid >> 1;
    const int hc = (tid & 1) * 2;
    const int sw = ((lr & 3) ^ ((lr >> 2) & 3)) << 2;
    const float* Ap = A + (size_t)(bm + lr) * K + hc * 4;
    const float* Bp = B + (size_t)(bn + lr) * K + hc * 4;
    const uint32_t dA0 = sb + (lr * 16 + ((4 * hc)     ^ sw)) * 4;
    const uint32_t dA1 = sb + (lr * 16 + ((4 * hc + 4) ^ sw)) * 4;
    const uint32_t dB0 = dA0 + GS * GBUF * 4;
    const uint32_t dB1 = dA1 + GS * GBUF * 4;

    const int cA0 = (4 * t) ^ (((g & 3) ^ ((g >> 2) & 3)) << 2);
    const int cA8 = (4 * t) ^ (((g & 3) ^ (((g >> 2) + 2) & 3)) << 2);
    int cB[4];
#pragma unroll
    for (int nt = 0; nt < 4; nt++)
        cB[nt] = (4 * t) ^ (((g & 3) ^ (((g >> 2) + 2 * nt) & 3)) << 2);

    float acc[4][4][4];
#pragma unroll
    for (int i = 0; i < 4; i++)
#pragma unroll
        for (int j = 0; j < 4; j++)
#pragma unroll
            for (int q = 0; q < 4; q++) acc[i][j][q] = 0.f;

    const int NC = K / 16;

#pragma unroll
    for (int c = 0; c < GS - 1; c++) {
        uint32_t so = (uint32_t)(c * GBUF * 4);
        const float* a = Ap + c * 16;
        const float* b = Bp + c * 16;
        cp16(dA0 + so, a);
        cp16(dA1 + so, a + 4);
        cp16(dB0 + so, b);
        cp16(dB1 + so, b + 4);
        CP_COMMIT();
    }

    for (int c = 0; c < NC; c++) {
        CP_WAIT(GS - 2);
        __syncthreads();

        int nc = c + GS - 1;
        if (nc < NC) {
            uint32_t so = (uint32_t)((nc % GS) * GBUF * 4);
            const float* a = Ap + nc * 16;
            const float* b = Bp + nc * 16;
            cp16(dA0 + so, a);
            cp16(dA1 + so, a + 4);
            cp16(dB0 + so, b);
            cp16(dB1 + so, b + 4);
        }
        CP_COMMIT();

        const int s = c % GS;
        const uint32_t* Ab = (const uint32_t*)(smem + s * GBUF);
        const uint32_t* Bb = (const uint32_t*)(smem + (GS + s) * GBUF);

        uint4 br[4];
#pragma unroll
        for (int nt = 0; nt < 4; nt++)
            br[nt] = *(const uint4*)&Bb[(wn + nt * 8 + g) * 16 + cB[nt]];

#pragma unroll
        for (int mt = 0; mt < 4; mt++) {
            const int r0 = wm + mt * 16 + g;
            uint4 ar0 = *(const uint4*)&Ab[r0 * 16 + cA0];
            uint4 ar1 = *(const uint4*)&Ab[(r0 + 8) * 16 + cA8];
#pragma unroll
            for (int nt = 0; nt < 4; nt++) {
                mma8v(acc[mt][nt], ar0.x, ar1.x, ar0.y, ar1.y, br[nt].x, br[nt].y);
                mma8v(acc[mt][nt], ar0.z, ar1.z, ar0.w, ar1.w, br[nt].z, br[nt].w);
            }
        }
    }

#pragma unroll
    for (int mt = 0; mt < 4; mt++) {
#pragma unroll
        for (int nt = 0; nt < 4; nt++) {
            int gcol = bn + wn + nt * 8 + 2 * t;
            float2 bv = *(const float2*)&bias[gcol];
            int r0 = bm + wm + mt * 16 + g;
#pragma unroll
            for (int hrow = 0; hrow < 2; hrow++) {
                int grow = r0 + hrow * 8;
                float c0 = acc[mt][nt][2 * hrow]     + bv.x;
                float c1 = acc[mt][nt][2 * hrow + 1] + bv.y;
                if (EPI == 1) {
                    size_t gidx = (size_t)grow * N + gcol;
                    float2 rv = *(const float2*)&res[gidx];
                    c0 += rv.x; c1 += rv.y;
                    *(float2*)&C[gidx] = make_float2(c0, c1);
                } else if (EPI == 0) {
                    size_t gidx = (size_t)grow * N + gcol;
                    *(float2*)&C[gidx] = make_float2(c0, c1);
                } else {
                    if (EPI == 2) {
                        c0 = c0 / (1.f + __expf(-1.702f * c0));
                        c1 = c1 / (1.f + __expf(-1.702f * c1));
                    }
                    int p  = gcol & 15;
                    int pp = ((p & 3) << 2) | (p >> 2);
                    size_t b16 = (size_t)grow * N + (gcol & ~15);
                    uint32_t u0, u1;
                    CVT_TF32(u0, c0); CVT_TF32(u1, c1);
                    ((uint32_t*)C)[b16 + pp]     = u0;
                    ((uint32_t*)C)[b16 + pp + 4] = u1;
                }
            }
        }
    }
}

// ---------------- Flash attention: 8 warps, 128 q rows per CTA ----------------
#define KS_STR 80
#define VP_STR 72
#define ATT_SMEM ((64 * KS_STR + 32 * VP_STR) * 4)   // 29696 B

__global__ __launch_bounds__(256, 2) void attn_mma(const float* __restrict__ qkv,
                                                   float* __restrict__ o)
{
    extern __shared__ float asmem[];
    float*    Ks = asmem;                            // [64][KS_STR]
    uint32_t* Vp = (uint32_t*)(asmem + 64 * KS_STR); // [32][VP_STR]
    const uint32_t ksb_addr = smem_u32(asmem);

    const int tid  = threadIdx.x;
    const int lane = tid & 31;
    const int w    = tid >> 5;                        // 0..7
    const int g = lane >> 2, t = lane & 3;
    const int qb = blockIdx.x * 128 + w * 16;
    const int h = blockIdx.y, n = blockIdx.z;

    const float qscale = 0.125f * 1.44269504088896f;

    uint32_t aq[8][4];
    {
        const uint32_t* qu = (const uint32_t*)qkv;
        size_t r0 = ((size_t)(qb + g) * NB + n) * E3 + h * DH;
        size_t r1 = ((size_t)(qb + g + 8) * NB + n) * E3 + h * DH;
#pragma unroll
        for (int blk = 0; blk < 4; blk++) {
#pragma unroll
            for (int hf = 0; hf < 2; hf++) {
                int off = blk * 16 + 4 * t + 2 * hf;
                uint2 q0 = *(const uint2*)&qu[r0 + off];
                uint2 q1 = *(const uint2*)&qu[r1 + off];
                int ch = 2 * blk + hf;
                CVT_TF32(aq[ch][0], __uint_as_float(q0.x) * qscale);
                CVT_TF32(aq[ch][1], __uint_as_float(q1.x) * qscale);
                CVT_TF32(aq[ch][2], __uint_as_float(q0.y) * qscale);
                CVT_TF32(aq[ch][3], __uint_as_float(q1.y) * qscale);
            }
        }
    }

    float oc[8][4];
#pragma unroll
    for (int i = 0; i < 8; i++)
#pragma unroll
        for (int j = 0; j < 4; j++) oc[i][j] = 0.f;
    float m0 = -1e30f, m1 = -1e30f, l0 = 0.f, l1 = 0.f;

    // K staging: 256 threads, row srow = tid>>2, block qblk = tid&3, 4x cp16 each
    const int srow = tid >> 2;                        // 0..63
    const int qblk = tid & 3;                         // 16-word block
    const int swu  = ((srow & 3) ^ ((srow >> 2) & 3));
    uint32_t kdst[4];
#pragma unroll
    for (int u = 0; u < 4; u++)
        kdst[u] = ksb_addr +
            (uint32_t)(KS_STR * srow + qblk * 16 + ((4 * u) ^ (swu << 2))) * 4;

    // V staging: pair vr = tid>>3 (0..31), 8-word chunk vq8 = (tid&7)*8
    const int vr  = tid >> 3;
    const int vq8 = (tid & 7) * 8;

    int fc[8];
#pragma unroll
    for (int nt = 0; nt < 8; nt++) {
        int r = nt * 8 + g;
        fc[nt] = KS_STR * r + ((4 * t) ^ ((((r & 3) ^ ((r >> 2) & 3))) << 2));
    }

    for (int kb = 0; kb < L_SEQ / 64; kb++) {
        // ---- V pair chunk to regs ----
        size_t vb0 = ((size_t)(kb * 64 + 2 * vr)     * NB + n) * E3 + 2 * EMB + h * DH + vq8;
        size_t vb1 = ((size_t)(kb * 64 + 2 * vr + 1) * NB + n) * E3 + 2 * EMB + h * DH + vq8;
        float4 vr0[2], vr1[2];
#pragma unroll
        for (int i = 0; i < 2; i++) {
            vr0[i] = *(const float4*)&qkv[vb0 + 4 * i];
            vr1[i] = *(const float4*)&qkv[vb1 + 4 * i];
        }
        __syncthreads();   // prior tile fully consumed

        // ---- K via cp.async ----
        {
            size_t kbase = ((size_t)(kb * 64 + srow) * NB + n) * E3 + EMB + h * DH + qblk * 16;
#pragma unroll
            for (int u = 0; u < 4; u++)
                cp16(kdst[u], &qkv[kbase + 4 * u]);
            CP_COMMIT();
        }

        // ---- V pack bf16x2 + STS ----
        {
            const float* f0 = (const float*)vr0;
            const float* f1 = (const float*)vr1;
            uint32_t* vp = &Vp[vr * VP_STR + vq8];
#pragma unroll
            for (int i = 0; i < 2; i++) {
                uint4 cv;
                PACK_BF16X2(cv.x, f0[4*i],   f1[4*i]);
                PACK_BF16X2(cv.y, f0[4*i+1], f1[4*i+1]);
                PACK_BF16X2(cv.z, f0[4*i+2], f1[4*i+2]);
                PACK_BF16X2(cv.w, f0[4*i+3], f1[4*i+3]);
                *(uint4*)&vp[4 * i] = cv;
            }
        }
        CP_WAIT(0);
        __syncthreads();

        // ---- S = Q K^T (tf32) ----
        float sc[8][4];
#pragma unroll
        for (int i = 0; i < 8; i++)
#pragma unroll
            for (int j = 0; j < 4; j++) sc[i][j] = 0.f;

        const uint32_t* ksb = (const uint32_t*)Ks;
#pragma unroll
        for (int nt = 0; nt < 8; nt++) {
#pragma unroll
            for (int blk = 0; blk < 4; blk++) {
                uint4 kbv = *(const uint4*)&ksb[fc[nt] + 16 * blk];
                mma8v(sc[nt], aq[2*blk][0],   aq[2*blk][1],   aq[2*blk][2],   aq[2*blk][3],   kbv.x, kbv.y);
                mma8v(sc[nt], aq[2*blk+1][0], aq[2*blk+1][1], aq[2*blk+1][2], aq[2*blk+1][3], kbv.z, kbv.w);
            }
        }

        // ---- online softmax ----
        float tm0 = -1e30f, tm1 = -1e30f;
#pragma unroll
        for (int nt = 0; nt < 8; nt++) {
            tm0 = fmaxf(tm0, fmaxf(sc[nt][0], sc[nt][1]));
            tm1 = fmaxf(tm1, fmaxf(sc[nt][2], sc[nt][3]));
        }
        tm0 = fmaxf(tm0, __shfl_xor_sync(0xffffffffu, tm0, 1));
        tm0 = fmaxf(tm0, __shfl_xor_sync(0xffffffffu, tm0, 2));
        tm1 = fmaxf(tm1, __shfl_xor_sync(0xffffffffu, tm1, 1));
        tm1 = fmaxf(tm1, __shfl_xor_sync(0xffffffffu, tm1, 2));

        float nm0 = fmaxf(m0, tm0), nm1 = fmaxf(m1, tm1);
        float al0 = ex2f(m0 - nm0), al1 = ex2f(m1 - nm1);
        m0 = nm0; m1 = nm1;

        float s0 = 0.f, s1 = 0.f;
#pragma unroll
        for (int nt = 0; nt < 8; nt++) {
            sc[nt][0] = ex2f(sc[nt][0] - m0);
            sc[nt][1] = ex2f(sc[nt][1] - m0);
            sc[nt][2] = ex2f(sc[nt][2] - m1);
            sc[nt][3] = ex2f(sc[nt][3] - m1);
            s0 += sc[nt][0] + sc[nt][1];
            s1 += sc[nt][2] + sc[nt][3];
        }
        s0 += __shfl_xor_sync(0xffffffffu, s0, 1);
        s0 += __shfl_xor_sync(0xffffffffu, s0, 2);
        s1 += __shfl_xor_sync(0xffffffffu, s1, 1);
        s1 += __shfl_xor_sync(0xffffffffu, s1, 2);
        l0 = l0 * al0 + s0;
        l1 = l1 * al1 + s1;
#pragma unroll
        for (int nt = 0; nt < 8; nt++) {
            oc[nt][0] *= al0; oc[nt][1] *= al0;
            oc[nt][2] *= al1; oc[nt][3] *= al1;
        }

        // ---- O += P V (bf16) ----
#pragma unroll
        for (int kk = 0; kk < 4; kk++) {
            uint32_t a0, a1, a2, a3;
            PACK_BF16X2(a0, sc[2*kk][0],   sc[2*kk][1]);
            PACK_BF16X2(a1, sc[2*kk][2],   sc[2*kk][3]);
            PACK_BF16X2(a2, sc[2*kk+1][0], sc[2*kk+1][1]);
            PACK_BF16X2(a3, sc[2*kk+1][2], sc[2*kk+1][3]);
#pragma unroll
            for (int nt = 0; nt < 8; nt++) {
                uint32_t b0 = Vp[(8 * kk + t)     * VP_STR + nt * 8 + g];
                uint32_t b1 = Vp[(8 * kk + t + 4) * VP_STR + nt * 8 + g];
                mma16bf(oc[nt], a0, a1, a2, a3, b0, b1);
            }
        }
    }

    float i0 = 1.f / l0, i1 = 1.f / l1;
    size_t o0 = ((size_t)(qb + g) * NB + n) * EMB + h * DH;
    size_t o1 = ((size_t)(qb + g + 8) * NB + n) * EMB + h * DH;
#pragma unroll
    for (int nt = 0; nt < 8; nt++) {
        int d = nt * 8 + 2 * t;
        uint2 u0, u1;
        CVT_TF32(u0.x, oc[nt][0] * i0); CVT_TF32(u0.y, oc[nt][1] * i0);
        CVT_TF32(u1.x, oc[nt][2] * i1); CVT_TF32(u1.y, oc[nt][3] * i1);
        *(uint2*)&((uint32_t*)o)[o0 + d] = u0;
        *(uint2*)&((uint32_t*)o)[o1 + d] = u1;
    }
}

// ---------------- launch ----------------
extern "C" void kernel_launch(void* const* d_in, const int* in_sizes, int n_in,
                              void* d_out, int out_size)
{
    const float* x      = (const float*)d_in[0];
    const float* ln1_w  = (const float*)d_in[1];
    const float* ln1_b  = (const float*)d_in[2];
    const float* w_qkv  = (const float*)d_in[3];
    const float* b_qkv  = (const float*)d_in[4];
    const float* w_out  = (const float*)d_in[5];
    const float* b_out  = (const float*)d_in[6];
    const float* ln2_w  = (const float*)d_in[7];
    const float* ln2_b  = (const float*)d_in[8];
    const float* w_fc   = (const float*)d_in[9];
    const float* b_fc   = (const float*)d_in[10];
    const float* w_proj = (const float*)d_in[11];
    const float* b_proj = (const float*)d_in[12];
    float* out = (float*)d_out;

    float *h, *qkv, *attn, *x1, *f, *wqkv, *wout, *wfc, *wproj;
    cudaGetSymbolAddress((void**)&h,     g_h);
    cudaGetSymbolAddress((void**)&qkv,   g_qkv);
    cudaGetSymbolAddress((void**)&attn,  g_attn);
    cudaGetSymbolAddress((void**)&x1,    g_x1);
    cudaGetSymbolAddress((void**)&f,     g_f);
    cudaGetSymbolAddress((void**)&wqkv,  g_wqkv);
    cudaGetSymbolAddress((void**)&wout,  g_wout);
    cudaGetSymbolAddress((void**)&wfc,   g_wfc);
    cudaGetSymbolAddress((void**)&wproj, g_wproj);

    cudaFuncSetAttribute(gemm_cp<1>, cudaFuncAttributeMaxDynamicSharedMemorySize, GT_SMEM);
    cudaFuncSetAttribute(gemm_cp<2>, cudaFuncAttributeMaxDynamicSharedMemorySize, GT_SMEM);
    cudaFuncSetAttribute(gemm_cp<3>, cudaFuncAttributeMaxDynamicSharedMemorySize, GT_SMEM);
    cudaFuncSetAttribute(attn_mma,   cudaFuncAttributeMaxDynamicSharedMemorySize, ATT_SMEM);

    int ptotal = S0 + S1 + S2 + S3;
    permute_all<<<(ptotal + 255) / 256, 256>>>(w_qkv, wqkv, w_out, wout,
                                               w_fc, wfc, w_proj, wproj);

    ln_kernel<<<ROWS / 8, 256>>>(x, ln1_w, ln1_b, h);
    gemm_cp<3><<<dim3(E3 / 128, ROWS / 128), 256, GT_SMEM>>>(h, wqkv, b_qkv, nullptr, qkv,
                                                             ROWS, E3, EMB);
    attn_mma<<<dim3(L_SEQ / 128, NHEAD, NB), 256, ATT_SMEM>>>(qkv, attn);
    gemm_cp<1><<<dim3(EMB / 128, ROWS / 128), 256, GT_SMEM>>>(attn, wout, b_out, x, x1,
                                                              ROWS, EMB, EMB);
    ln_kernel<<<ROWS / 8, 256>>>(x1, ln2_w, ln2_b, h);
    gemm_cp<2><<<dim3(E4 / 128, ROWS / 128), 256, GT_SMEM>>>(h, wfc, b_fc, nullptr, f,
                                                             ROWS, E4, EMB);
    gemm_cp<1><<<dim3(EMB / 128, ROWS / 128), 256, GT_SMEM>>>(f, wproj, b_proj, x1, out,
                                                              ROWS, EMB, E4);
}